// round 11
// baseline (speedup 1.0000x reference)
#include <cuda_runtime.h>
#include <cuda_bf16.h>
#include <cuda_fp16.h>
#include <stdint.h>

#define F 128
#define NMAX 100000
#define EMAX 1700000   // E + N self loops

// ---------------- scratch (alloc-free: __device__ globals) ----------------
__device__ __half g_h[NMAX * F];                // transformed features h = feat @ W (fp16)
__device__ __nv_bfloat16 g_xh[NMAX * F];        // current layer input, bf16 hi
__device__ __nv_bfloat16 g_xl[NMAX * F];        // current layer input, bf16 lo
__device__ __nv_bfloat16 g_wh[3][F * F];        // W bf16 hi per layer
__device__ __nv_bfloat16 g_wl[3][F * F];        // W bf16 lo per layer
__device__ float g_asrc[NMAX];
__device__ float g_adst[NMAX];
__device__ int   g_deg[NMAX];
__device__ int   g_rowptr[NMAX + 1];
__device__ int   g_cursor[NMAX];
__device__ int   g_srcs[EMAX];                  // src indices sorted by dst (CSR)
__device__ int   g_bsum[256];                   // scan block sums
__device__ int   g_bpre[257];                   // scan block prefixes (+ total)

// ---------------- helpers ----------------
__device__ __forceinline__ uint32_t smem_u32(const void* p) {
    uint32_t a;
    asm("{ .reg .u64 t; cvta.to.shared.u64 t, %1; cvt.u32.u64 %0, t; }" : "=r"(a) : "l"(p));
    return a;
}
__device__ __forceinline__ void ldsm_x4(uint32_t* r, uint32_t addr) {
    asm volatile("ldmatrix.sync.aligned.m8n8.x4.shared.b16 {%0,%1,%2,%3}, [%4];"
                 : "=r"(r[0]), "=r"(r[1]), "=r"(r[2]), "=r"(r[3]) : "r"(addr));
}
__device__ __forceinline__ void ldsm_x4_t(uint32_t* r, uint32_t addr) {
    asm volatile("ldmatrix.sync.aligned.m8n8.x4.trans.shared.b16 {%0,%1,%2,%3}, [%4];"
                 : "=r"(r[0]), "=r"(r[1]), "=r"(r[2]), "=r"(r[3]) : "r"(addr));
}
__device__ __forceinline__ void mma_bf16(float* c, const uint32_t* a, const uint32_t* b) {
    asm volatile("mma.sync.aligned.m16n8k16.row.col.f32.bf16.bf16.f32 "
                 "{%0,%1,%2,%3}, {%4,%5,%6,%7}, {%8,%9}, {%0,%1,%2,%3};"
                 : "+f"(c[0]), "+f"(c[1]), "+f"(c[2]), "+f"(c[3])
                 : "r"(a[0]), "r"(a[1]), "r"(a[2]), "r"(a[3]), "r"(b[0]), "r"(b[1]));
}
__device__ __forceinline__ void split_bf16(float x, __nv_bfloat16& h, __nv_bfloat16& l) {
    h = __float2bfloat16_rn(x);
    l = __float2bfloat16_rn(x - __bfloat162float(h));
}
__device__ __forceinline__ void split4_store(float4 r, __nv_bfloat16* ph, __nv_bfloat16* pl) {
    __nv_bfloat16 h0, l0, h1, l1, h2, l2, h3, l3;
    split_bf16(r.x, h0, l0); split_bf16(r.y, h1, l1);
    split_bf16(r.z, h2, l2); split_bf16(r.w, h3, l3);
    uint2 hp, lp;
    hp.x = (uint32_t)__bfloat16_as_ushort(h0) | ((uint32_t)__bfloat16_as_ushort(h1) << 16);
    hp.y = (uint32_t)__bfloat16_as_ushort(h2) | ((uint32_t)__bfloat16_as_ushort(h3) << 16);
    lp.x = (uint32_t)__bfloat16_as_ushort(l0) | ((uint32_t)__bfloat16_as_ushort(l1) << 16);
    lp.y = (uint32_t)__bfloat16_as_ushort(l2) | ((uint32_t)__bfloat16_as_ushort(l3) << 16);
    *(uint2*)ph = hp;
    *(uint2*)pl = lp;
}

// ---------------- input / weight splitting ----------------
__global__ void k_split_x(const float* __restrict__ x, int total4) {
    int i = blockIdx.x * blockDim.x + threadIdx.x;
    if (i >= total4) return;
    float4 v = ((const float4*)x)[i];
    split4_store(v, &g_xh[i * 4], &g_xl[i * 4]);
}
__global__ void k_prepW_all(const float* __restrict__ W0, const float* __restrict__ W1,
                            const float* __restrict__ W2) {
    int i = blockIdx.x * blockDim.x + threadIdx.x;
    if (i >= 3 * 4096) return;
    int l = i >> 12, j = i & 4095;
    const float* W = (l == 0) ? W0 : (l == 1) ? W1 : W2;
    float4 v = ((const float4*)W)[j];
    split4_store(v, &g_wh[l][j * 4], &g_wl[l][j * 4]);
}

// ---------------- CSR build ----------------
__global__ void k_zero_deg(int N) {
    int i = blockIdx.x * blockDim.x + threadIdx.x;
    if (i < N) g_deg[i] = 0;
}
__global__ void k_count(const int* __restrict__ ei, int E, int N) {
    int j = blockIdx.x * blockDim.x + threadIdx.x;
    if (j >= E + N) return;
    int d = (j < E) ? ei[E + j] : (j - E);
    atomicAdd(&g_deg[d], 1);
}
__global__ void k_scan1(int N) {
    __shared__ int s[256];
    int t = threadIdx.x, b = blockIdx.x;
    int i0 = b * 1024 + t * 4;
    int sum = 0;
#pragma unroll
    for (int j = 0; j < 4; j++)
        if (i0 + j < N) sum += g_deg[i0 + j];
    s[t] = sum;
    __syncthreads();
#pragma unroll
    for (int off = 128; off; off >>= 1) {
        if (t < off) s[t] += s[t + off];
        __syncthreads();
    }
    if (t == 0) g_bsum[b] = s[0];
}
__global__ void k_scan2(int nb) {
    __shared__ int s[256];
    int t = threadIdx.x;
    int v = (t < nb) ? g_bsum[t] : 0;
    s[t] = v;
    __syncthreads();
#pragma unroll
    for (int off = 1; off < 256; off <<= 1) {
        int u = (t >= off) ? s[t - off] : 0;
        __syncthreads();
        s[t] += u;
        __syncthreads();
    }
    if (t <= nb) g_bpre[t] = (t == 0) ? 0 : s[t - 1];
    if (t == 255) g_bpre[256] = s[255];
}
__global__ void k_scan3(int N, int nb) {
    __shared__ int s[256];
    int t = threadIdx.x, b = blockIdx.x;
    int i0 = b * 1024 + t * 4;
    int d[4];
    int sum = 0;
#pragma unroll
    for (int j = 0; j < 4; j++) {
        d[j] = (i0 + j < N) ? g_deg[i0 + j] : 0;
        sum += d[j];
    }
    s[t] = sum;
    __syncthreads();
#pragma unroll
    for (int off = 1; off < 256; off <<= 1) {
        int u = (t >= off) ? s[t - off] : 0;
        __syncthreads();
        s[t] += u;
        __syncthreads();
    }
    int run = g_bpre[b] + s[t] - sum;
#pragma unroll
    for (int j = 0; j < 4; j++) {
        if (i0 + j < N) {
            g_rowptr[i0 + j] = run;
            g_cursor[i0 + j] = run;
        }
        run += d[j];
    }
    if (b == 0 && t == 0) g_rowptr[N] = g_bpre[nb];
}
__global__ void k_scatter(const int* __restrict__ ei, int E, int N) {
    int j = blockIdx.x * blockDim.x + threadIdx.x;
    if (j >= E + N) return;
    int sIdx, d;
    if (j < E) { sIdx = ei[j]; d = ei[E + j]; }
    else       { sIdx = j - E; d = j - E; }
    int pos = atomicAdd(&g_cursor[d], 1);
    g_srcs[pos] = sIdx;
}

// ---------------- bf16x3 tensor-core GEMM (mma.sync) + fused alpha dots ----------------
// M-tile 64, 256 threads, 8 warps 2(M)x4(N), warp tile 32x32.
// __launch_bounds__(256,2): 2 CTAs/SM -> RF 2*256*128 = 65536 (exact), smem 2*~104KB.
#define AS_STRIDE 136
#define A_TILE_B (64 * AS_STRIDE * 2)    // 17408
#define B_TILE_B (128 * AS_STRIDE * 2)   // 34816
#define OFF_AH 0
#define OFF_AL (A_TILE_B)
#define OFF_BH (2 * A_TILE_B)
#define OFF_BL (2 * A_TILE_B + B_TILE_B)
#define OFF_SAS (2 * A_TILE_B + 2 * B_TILE_B)
#define OFF_SAD (OFF_SAS + 512)
#define OFF_SUA (OFF_SAD + 512)
#define OFF_SUD (OFF_SUA + 256)
#define GEMM_SMEM (OFF_SUD + 256)

__global__ void __launch_bounds__(256, 2)
k_gemm_mma(int layer, const float* __restrict__ av_s, const float* __restrict__ av_d, int Nn) {
    extern __shared__ char smem[];
    const uint32_t sb = smem_u32(smem);
    const int tid = threadIdx.x, lane = tid & 31, wid = tid >> 5;
    const int row0 = blockIdx.x * 64;

    float* s_as = (float*)(smem + OFF_SAS);
    float* s_ad = (float*)(smem + OFF_SAD);
    float* s_ua = (float*)(smem + OFF_SUA);
    float* s_ud = (float*)(smem + OFF_SUD);
    if (tid < 128) {
        s_as[tid] = av_s[tid];
        s_ad[tid] = av_d[tid];
    }
    if (tid < 64) { s_ua[tid] = 0.f; s_ud[tid] = 0.f; }

    {   // stage A: 64 rows, 4 threads/row, 32 bf16 (4 uint4) per image
        int r = tid >> 2, seg = (tid & 3) * 32;
        int gr = min(row0 + r, Nn - 1);
        const uint4* sAh = (const uint4*)&g_xh[(size_t)gr * 128 + seg];
        const uint4* sAl = (const uint4*)&g_xl[(size_t)gr * 128 + seg];
        uint4* dAh = (uint4*)((__nv_bfloat16*)(smem + OFF_AH) + r * AS_STRIDE + seg);
        uint4* dAl = (uint4*)((__nv_bfloat16*)(smem + OFF_AL) + r * AS_STRIDE + seg);
#pragma unroll
        for (int j = 0; j < 4; j++) {
            dAh[j] = sAh[j];
            dAl[j] = sAl[j];
        }
    }
    {   // stage B: 128 rows, 2 threads/row, 64 bf16 (8 uint4) per image
        int r = tid >> 1, seg = (tid & 1) * 64;
        const uint4* sBh = (const uint4*)&g_wh[layer][r * 128 + seg];
        const uint4* sBl = (const uint4*)&g_wl[layer][r * 128 + seg];
        uint4* dBh = (uint4*)((__nv_bfloat16*)(smem + OFF_BH) + r * AS_STRIDE + seg);
        uint4* dBl = (uint4*)((__nv_bfloat16*)(smem + OFF_BL) + r * AS_STRIDE + seg);
#pragma unroll
        for (int j = 0; j < 8; j++) {
            dBh[j] = sBh[j];
            dBl[j] = sBl[j];
        }
    }
    __syncthreads();

    const int wm = wid & 1, wn = wid >> 1;
    const int wrow = wm * 32, wcol = wn * 32;
    float acc[2][4][4];
#pragma unroll
    for (int i = 0; i < 2; i++)
#pragma unroll
        for (int j = 0; j < 4; j++)
#pragma unroll
            for (int q = 0; q < 4; q++) acc[i][j][q] = 0.f;

    const int lr = lane & 15, lc = lane >> 4;
#pragma unroll
    for (int pass = 0; pass < 3; pass++) {
        uint32_t aoff = sb + ((pass == 1) ? OFF_AL : OFF_AH);
        uint32_t boff = sb + ((pass == 2) ? OFF_BL : OFF_BH);
#pragma unroll
        for (int ks = 0; ks < 8; ks++) {
            int k0 = ks * 16;
            uint32_t a[2][4], b[2][4];
#pragma unroll
            for (int mt = 0; mt < 2; mt++)
                ldsm_x4(a[mt], aoff + ((wrow + mt * 16 + lr) * AS_STRIDE + lc * 8 + k0) * 2);
#pragma unroll
            for (int ng = 0; ng < 2; ng++)
                ldsm_x4_t(b[ng], boff + ((k0 + lr) * AS_STRIDE + wcol + ng * 16 + lc * 8) * 2);
#pragma unroll
            for (int mt = 0; mt < 2; mt++)
#pragma unroll
                for (int nt = 0; nt < 4; nt++)
                    mma_bf16(acc[mt][nt], a[mt], &b[nt >> 1][(nt & 1) * 2]);
        }
    }

    float pa[4] = {0.f, 0.f, 0.f, 0.f}, pd[4] = {0.f, 0.f, 0.f, 0.f};
#pragma unroll
    for (int mt = 0; mt < 2; mt++) {
#pragma unroll
        for (int half = 0; half < 2; half++) {
            int rl = wrow + mt * 16 + half * 8 + (lane >> 2);
            int gr = row0 + rl;
            bool ok = gr < Nn;
#pragma unroll
            for (int nt = 0; nt < 4; nt++) {
                int cl = wcol + nt * 8 + (lane & 3) * 2;
                float v0 = acc[mt][nt][half * 2 + 0];
                float v1 = acc[mt][nt][half * 2 + 1];
                if (ok) *(__half2*)&g_h[(size_t)gr * 128 + cl] = __floats2half2_rn(v0, v1);
                pa[mt * 2 + half] += v0 * s_as[cl] + v1 * s_as[cl + 1];
                pd[mt * 2 + half] += v0 * s_ad[cl] + v1 * s_ad[cl + 1];
            }
        }
    }
#pragma unroll
    for (int i = 0; i < 4; i++) {
        int rl = wrow + (i >> 1) * 16 + (i & 1) * 8 + (lane >> 2);
        atomicAdd(&s_ua[rl], pa[i]);
        atomicAdd(&s_ud[rl], pd[i]);
    }
    __syncthreads();
    if (tid < 64 && row0 + tid < Nn) {
        g_asrc[row0 + tid] = s_ua[tid];
        g_adst[row0 + tid] = s_ud[tid];
    }
}

// ---------------- softmax aggregation, one warp per dst ----------------
// fast path for deg<=32 (one batch): pass-1 values kept in registers.
__global__ void k_aggregate(const float* __restrict__ bias, float* __restrict__ outp,
                            int N, int write_final) {
    int warp = (blockIdx.x * blockDim.x + threadIdx.x) >> 5;
    int lane = threadIdx.x & 31;
    if (warp >= N) return;

    int beg = g_rowptr[warp];
    int end = g_rowptr[warp + 1];
    float ad = g_adst[warp];

    float4 acc = make_float4(0.f, 0.f, 0.f, 0.f);
    float denom = 0.f;

    if (end - beg <= 32) {
        // single batch: one gather of (srcs, asrc), no second pass
        int e = beg + lane;
        int s = 0;
        float v = -1e30f;
        if (e < end) {
            s = __ldg(&g_srcs[e]);
            float t = __ldg(&g_asrc[s]) + ad;
            v = t > 0.f ? t : 0.2f * t;
        }
        float m = v;
#pragma unroll
        for (int off = 16; off; off >>= 1)
            m = fmaxf(m, __shfl_xor_sync(0xffffffffu, m, off));
        float w = __expf(v - m);      // invalid lanes: exp(-huge) = 0
        denom = w;
        int cnt = end - beg;
        for (int i = 0; i < cnt; i++) {
            float wi = __shfl_sync(0xffffffffu, w, i);
            int   si = __shfl_sync(0xffffffffu, s, i);
            uint2 raw = __ldg((const uint2*)&g_h[(size_t)si * 128 + lane * 4]);
            __half2 h01 = *reinterpret_cast<__half2*>(&raw.x);
            __half2 h23 = *reinterpret_cast<__half2*>(&raw.y);
            float2 f01 = __half22float2(h01);
            float2 f23 = __half22float2(h23);
            acc.x += wi * f01.x; acc.y += wi * f01.y;
            acc.z += wi * f23.x; acc.w += wi * f23.y;
        }
    } else {
        // pass 1: segment max
        float m = -1e30f;
        for (int e = beg + lane; e < end; e += 32) {
            int s = __ldg(&g_srcs[e]);
            float v = __ldg(&g_asrc[s]) + ad;
            v = v > 0.f ? v : 0.2f * v;
            m = fmaxf(m, v);
        }
#pragma unroll
        for (int off = 16; off; off >>= 1)
            m = fmaxf(m, __shfl_xor_sync(0xffffffffu, m, off));
        // pass 2
        for (int base = beg; base < end; base += 32) {
            int e = base + lane;
            float w = 0.f;
            int s = 0;
            if (e < end) {
                s = __ldg(&g_srcs[e]);
                float v = __ldg(&g_asrc[s]) + ad;
                v = v > 0.f ? v : 0.2f * v;
                w = __expf(v - m);
            }
            denom += w;
            int cnt = min(32, end - base);
            for (int i = 0; i < cnt; i++) {
                float wi = __shfl_sync(0xffffffffu, w, i);
                int   si = __shfl_sync(0xffffffffu, s, i);
                uint2 raw = __ldg((const uint2*)&g_h[(size_t)si * 128 + lane * 4]);
                __half2 h01 = *reinterpret_cast<__half2*>(&raw.x);
                __half2 h23 = *reinterpret_cast<__half2*>(&raw.y);
                float2 f01 = __half22float2(h01);
                float2 f23 = __half22float2(h23);
                acc.x += wi * f01.x; acc.y += wi * f01.y;
                acc.z += wi * f23.x; acc.w += wi * f23.y;
            }
        }
    }
#pragma unroll
    for (int off = 16; off; off >>= 1)
        denom += __shfl_xor_sync(0xffffffffu, denom, off);

    float inv = 1.f / denom;
    float4 bv = *(const float4*)&bias[lane * 4];
    float4 r;
    r.x = acc.x * inv + bv.x;
    r.y = acc.y * inv + bv.y;
    r.z = acc.z * inv + bv.z;
    r.w = acc.w * inv + bv.w;
    if (write_final) {
        *(float4*)&outp[(size_t)warp * 128 + lane * 4] = r;
    } else {
        r.x = r.x > 0.f ? r.x : expm1f(r.x);
        r.y = r.y > 0.f ? r.y : expm1f(r.y);
        r.z = r.z > 0.f ? r.z : expm1f(r.z);
        r.w = r.w > 0.f ? r.w : expm1f(r.w);
        size_t idx = (size_t)warp * 128 + lane * 4;
        split4_store(r, &g_xh[idx], &g_xl[idx]);
    }
}

// ---------------- launch ----------------
extern "C" void kernel_launch(void* const* d_in, const int* in_sizes, int n_in,
                              void* d_out, int out_size) {
    const float* x  = (const float*)d_in[0];
    const int*   ei = (const int*)d_in[1];
    int N  = in_sizes[0] / F;
    int E  = in_sizes[1] / 2;
    int ET = E + N;
    int nb = (N + 1023) / 1024;

    static int smem_set = 0;
    if (!smem_set) {
        cudaFuncSetAttribute(k_gemm_mma, cudaFuncAttributeMaxDynamicSharedMemorySize, GEMM_SMEM);
        smem_set = 1;
    }

    int warp_blocks = (N * 32 + 255) / 256;
    int gemm_blocks = (N + 63) / 64;

    // launch #4 = k_gemm_mma (ncu captures the 4th launch)
    k_split_x<<<(N * 32 + 255) / 256, 256>>>(x, N * 32);
    k_prepW_all<<<48, 256>>>((const float*)d_in[2], (const float*)d_in[6], (const float*)d_in[10]);
    k_zero_deg<<<(N + 255) / 256, 256>>>(N);
    k_gemm_mma<<<gemm_blocks, 256, GEMM_SMEM>>>(0, (const float*)d_in[3], (const float*)d_in[4], N);
    k_count<<<(ET + 255) / 256, 256>>>(ei, E, N);
    k_scan1<<<nb, 256>>>(N);
    k_scan2<<<1, 256>>>(nb);
    k_scan3<<<nb, 256>>>(N, nb);
    k_scatter<<<(ET + 255) / 256, 256>>>(ei, E, N);

    for (int l = 0; l < 3; l++) {
        const float* as = (const float*)d_in[3 + 4 * l];
        const float* ad = (const float*)d_in[4 + 4 * l];
        const float* b  = (const float*)d_in[5 + 4 * l];
        if (l > 0)
            k_gemm_mma<<<gemm_blocks, 256, GEMM_SMEM>>>(l, as, ad, N);
        k_aggregate<<<warp_blocks, 256>>>(b, l == 2 ? (float*)d_out : nullptr, N, l == 2 ? 1 : 0);
    }
}

// round 12
// speedup vs baseline: 1.0894x; 1.0894x over previous
#include <cuda_runtime.h>
#include <cuda_bf16.h>
#include <cuda_fp16.h>
#include <stdint.h>

#define F 128
#define NMAX 100000
#define EMAX 1700000   // E + N self loops

// ---------------- scratch (alloc-free: __device__ globals) ----------------
__device__ __half g_h[NMAX * F];                // transformed features h = feat @ W (fp16)
__device__ __nv_bfloat16 g_xh[NMAX * F];        // current layer input, bf16 hi
__device__ __nv_bfloat16 g_xl[NMAX * F];        // current layer input, bf16 lo
__device__ __nv_bfloat16 g_wh[3][F * F];        // W bf16 hi per layer
__device__ __nv_bfloat16 g_wl[3][F * F];        // W bf16 lo per layer
__device__ float g_asrc[NMAX];
__device__ float g_adst[NMAX];
__device__ int   g_deg[NMAX];
__device__ int   g_rowptr[NMAX + 1];
__device__ int   g_cursor[NMAX];
__device__ int   g_srcs[EMAX];                  // src indices sorted by dst (CSR)
__device__ int   g_bsum[256];                   // scan block sums
__device__ int   g_bpre[257];                   // scan block prefixes (+ total)

// ---------------- helpers ----------------
__device__ __forceinline__ uint32_t smem_u32(const void* p) {
    uint32_t a;
    asm("{ .reg .u64 t; cvta.to.shared.u64 t, %1; cvt.u32.u64 %0, t; }" : "=r"(a) : "l"(p));
    return a;
}
__device__ __forceinline__ void ldsm_x4(uint32_t* r, uint32_t addr) {
    asm volatile("ldmatrix.sync.aligned.m8n8.x4.shared.b16 {%0,%1,%2,%3}, [%4];"
                 : "=r"(r[0]), "=r"(r[1]), "=r"(r[2]), "=r"(r[3]) : "r"(addr));
}
__device__ __forceinline__ void ldsm_x4_t(uint32_t* r, uint32_t addr) {
    asm volatile("ldmatrix.sync.aligned.m8n8.x4.trans.shared.b16 {%0,%1,%2,%3}, [%4];"
                 : "=r"(r[0]), "=r"(r[1]), "=r"(r[2]), "=r"(r[3]) : "r"(addr));
}
__device__ __forceinline__ void mma_bf16(float* c, const uint32_t* a, const uint32_t* b) {
    asm volatile("mma.sync.aligned.m16n8k16.row.col.f32.bf16.bf16.f32 "
                 "{%0,%1,%2,%3}, {%4,%5,%6,%7}, {%8,%9}, {%0,%1,%2,%3};"
                 : "+f"(c[0]), "+f"(c[1]), "+f"(c[2]), "+f"(c[3])
                 : "r"(a[0]), "r"(a[1]), "r"(a[2]), "r"(a[3]), "r"(b[0]), "r"(b[1]));
}
__device__ __forceinline__ void split_bf16(float x, __nv_bfloat16& h, __nv_bfloat16& l) {
    h = __float2bfloat16_rn(x);
    l = __float2bfloat16_rn(x - __bfloat162float(h));
}
__device__ __forceinline__ void split4_store(float4 r, __nv_bfloat16* ph, __nv_bfloat16* pl) {
    __nv_bfloat16 h0, l0, h1, l1, h2, l2, h3, l3;
    split_bf16(r.x, h0, l0); split_bf16(r.y, h1, l1);
    split_bf16(r.z, h2, l2); split_bf16(r.w, h3, l3);
    uint2 hp, lp;
    hp.x = (uint32_t)__bfloat16_as_ushort(h0) | ((uint32_t)__bfloat16_as_ushort(h1) << 16);
    hp.y = (uint32_t)__bfloat16_as_ushort(h2) | ((uint32_t)__bfloat16_as_ushort(h3) << 16);
    lp.x = (uint32_t)__bfloat16_as_ushort(l0) | ((uint32_t)__bfloat16_as_ushort(l1) << 16);
    lp.y = (uint32_t)__bfloat16_as_ushort(l2) | ((uint32_t)__bfloat16_as_ushort(l3) << 16);
    *(uint2*)ph = hp;
    *(uint2*)pl = lp;
}

// ---------------- input / weight splitting ----------------
__global__ void k_split_x(const float* __restrict__ x, int total4) {
    int i = blockIdx.x * blockDim.x + threadIdx.x;
    if (i >= total4) return;
    float4 v = ((const float4*)x)[i];
    split4_store(v, &g_xh[i * 4], &g_xl[i * 4]);
}
__global__ void k_prepW_all(const float* __restrict__ W0, const float* __restrict__ W1,
                            const float* __restrict__ W2) {
    int i = blockIdx.x * blockDim.x + threadIdx.x;
    if (i >= 3 * 4096) return;
    int l = i >> 12, j = i & 4095;
    const float* W = (l == 0) ? W0 : (l == 1) ? W1 : W2;
    float4 v = ((const float4*)W)[j];
    split4_store(v, &g_wh[l][j * 4], &g_wl[l][j * 4]);
}

// ---------------- CSR build ----------------
__global__ void k_zero_deg(int N) {
    int i = blockIdx.x * blockDim.x + threadIdx.x;
    if (i < N) g_deg[i] = 0;
}
__global__ void k_count(const int* __restrict__ ei, int E, int N) {
    int j = blockIdx.x * blockDim.x + threadIdx.x;
    if (j >= E + N) return;
    int d = (j < E) ? ei[E + j] : (j - E);
    atomicAdd(&g_deg[d], 1);
}
__global__ void k_scan1(int N) {
    __shared__ int s[256];
    int t = threadIdx.x, b = blockIdx.x;
    int i0 = b * 1024 + t * 4;
    int sum = 0;
#pragma unroll
    for (int j = 0; j < 4; j++)
        if (i0 + j < N) sum += g_deg[i0 + j];
    s[t] = sum;
    __syncthreads();
#pragma unroll
    for (int off = 128; off; off >>= 1) {
        if (t < off) s[t] += s[t + off];
        __syncthreads();
    }
    if (t == 0) g_bsum[b] = s[0];
}
__global__ void k_scan2(int nb) {
    __shared__ int s[256];
    int t = threadIdx.x;
    int v = (t < nb) ? g_bsum[t] : 0;
    s[t] = v;
    __syncthreads();
#pragma unroll
    for (int off = 1; off < 256; off <<= 1) {
        int u = (t >= off) ? s[t - off] : 0;
        __syncthreads();
        s[t] += u;
        __syncthreads();
    }
    if (t <= nb) g_bpre[t] = (t == 0) ? 0 : s[t - 1];
    if (t == 255) g_bpre[256] = s[255];
}
__global__ void k_scan3(int N, int nb) {
    __shared__ int s[256];
    int t = threadIdx.x, b = blockIdx.x;
    int i0 = b * 1024 + t * 4;
    int d[4];
    int sum = 0;
#pragma unroll
    for (int j = 0; j < 4; j++) {
        d[j] = (i0 + j < N) ? g_deg[i0 + j] : 0;
        sum += d[j];
    }
    s[t] = sum;
    __syncthreads();
#pragma unroll
    for (int off = 1; off < 256; off <<= 1) {
        int u = (t >= off) ? s[t - off] : 0;
        __syncthreads();
        s[t] += u;
        __syncthreads();
    }
    int run = g_bpre[b] + s[t] - sum;
#pragma unroll
    for (int j = 0; j < 4; j++) {
        if (i0 + j < N) {
            g_rowptr[i0 + j] = run;
            g_cursor[i0 + j] = run;
        }
        run += d[j];
    }
    if (b == 0 && t == 0) g_rowptr[N] = g_bpre[nb];
}
__global__ void k_scatter(const int* __restrict__ ei, int E, int N) {
    int j = blockIdx.x * blockDim.x + threadIdx.x;
    if (j >= E + N) return;
    int sIdx, d;
    if (j < E) { sIdx = ei[j]; d = ei[E + j]; }
    else       { sIdx = j - E; d = j - E; }
    int pos = atomicAdd(&g_cursor[d], 1);
    g_srcs[pos] = sIdx;
}

// ---------------- bf16x3 tensor-core GEMM (R10 config, best measured) ----------------
// 512 threads, 16 warps in 4(M) x 4(N); warp tile 32x32; M-tile 128.
#define AS_STRIDE 136
#define TILE_B (128 * AS_STRIDE * 2)
#define OFF_AH 0
#define OFF_AL (TILE_B)
#define OFF_BH (2 * TILE_B)
#define OFF_BL (3 * TILE_B)
#define OFF_SAS (4 * TILE_B)
#define OFF_SAD (OFF_SAS + 512)
#define OFF_SUA (OFF_SAD + 512)
#define OFF_SUD (OFF_SUA + 512)
#define GEMM_SMEM (OFF_SUD + 512)

__global__ void __launch_bounds__(512)
k_gemm_mma(int layer, const float* __restrict__ av_s, const float* __restrict__ av_d, int Nn) {
    extern __shared__ char smem[];
    const uint32_t sb = smem_u32(smem);
    const int tid = threadIdx.x, lane = tid & 31, wid = tid >> 5;
    const int row0 = blockIdx.x * 128;

    float* s_as = (float*)(smem + OFF_SAS);
    float* s_ad = (float*)(smem + OFF_SAD);
    float* s_ua = (float*)(smem + OFF_SUA);
    float* s_ud = (float*)(smem + OFF_SUD);
    if (tid < 128) {
        s_as[tid] = av_s[tid];
        s_ad[tid] = av_d[tid];
        s_ua[tid] = 0.f;
        s_ud[tid] = 0.f;
    }

    {   // stage: pure copies (pre-split bf16 in global); 4 threads per 128-elem row
        int r = tid >> 2, seg = (tid & 3) * 32;
        int gr = min(row0 + r, Nn - 1);
        const uint4* sAh = (const uint4*)&g_xh[(size_t)gr * 128 + seg];
        const uint4* sAl = (const uint4*)&g_xl[(size_t)gr * 128 + seg];
        const uint4* sBh = (const uint4*)&g_wh[layer][r * 128 + seg];
        const uint4* sBl = (const uint4*)&g_wl[layer][r * 128 + seg];
        uint4* dAh = (uint4*)((__nv_bfloat16*)(smem + OFF_AH) + r * AS_STRIDE + seg);
        uint4* dAl = (uint4*)((__nv_bfloat16*)(smem + OFF_AL) + r * AS_STRIDE + seg);
        uint4* dBh = (uint4*)((__nv_bfloat16*)(smem + OFF_BH) + r * AS_STRIDE + seg);
        uint4* dBl = (uint4*)((__nv_bfloat16*)(smem + OFF_BL) + r * AS_STRIDE + seg);
#pragma unroll
        for (int j = 0; j < 4; j++) {
            dAh[j] = sAh[j];
            dAl[j] = sAl[j];
            dBh[j] = sBh[j];
            dBl[j] = sBl[j];
        }
    }
    __syncthreads();

    const int wm = wid & 3, wn = wid >> 2;
    const int wrow = wm * 32, wcol = wn * 32;
    float acc[2][4][4];
#pragma unroll
    for (int i = 0; i < 2; i++)
#pragma unroll
        for (int j = 0; j < 4; j++)
#pragma unroll
            for (int q = 0; q < 4; q++) acc[i][j][q] = 0.f;

    const int lr = lane & 15, lc = lane >> 4;
#pragma unroll
    for (int pass = 0; pass < 3; pass++) {
        uint32_t aoff = sb + ((pass == 1) ? OFF_AL : OFF_AH);
        uint32_t boff = sb + ((pass == 2) ? OFF_BL : OFF_BH);
#pragma unroll
        for (int ks = 0; ks < 8; ks++) {
            int k0 = ks * 16;
            uint32_t a[2][4], b[2][4];
#pragma unroll
            for (int mt = 0; mt < 2; mt++)
                ldsm_x4(a[mt], aoff + ((wrow + mt * 16 + lr) * AS_STRIDE + lc * 8 + k0) * 2);
#pragma unroll
            for (int ng = 0; ng < 2; ng++)
                ldsm_x4_t(b[ng], boff + ((k0 + lr) * AS_STRIDE + wcol + ng * 16 + lc * 8) * 2);
#pragma unroll
            for (int mt = 0; mt < 2; mt++)
#pragma unroll
                for (int nt = 0; nt < 4; nt++)
                    mma_bf16(acc[mt][nt], a[mt], &b[nt >> 1][(nt & 1) * 2]);
        }
    }

    float pa[4] = {0.f, 0.f, 0.f, 0.f}, pd[4] = {0.f, 0.f, 0.f, 0.f};
#pragma unroll
    for (int mt = 0; mt < 2; mt++) {
#pragma unroll
        for (int half = 0; half < 2; half++) {
            int rl = wrow + mt * 16 + half * 8 + (lane >> 2);
            int gr = row0 + rl;
            bool ok = gr < Nn;
#pragma unroll
            for (int nt = 0; nt < 4; nt++) {
                int cl = wcol + nt * 8 + (lane & 3) * 2;
                float v0 = acc[mt][nt][half * 2 + 0];
                float v1 = acc[mt][nt][half * 2 + 1];
                if (ok) *(__half2*)&g_h[(size_t)gr * 128 + cl] = __floats2half2_rn(v0, v1);
                pa[mt * 2 + half] += v0 * s_as[cl] + v1 * s_as[cl + 1];
                pd[mt * 2 + half] += v0 * s_ad[cl] + v1 * s_ad[cl + 1];
            }
        }
    }
#pragma unroll
    for (int i = 0; i < 4; i++) {
        int rl = wrow + (i >> 1) * 16 + (i & 1) * 8 + (lane >> 2);
        atomicAdd(&s_ua[rl], pa[i]);
        atomicAdd(&s_ud[rl], pd[i]);
    }
    __syncthreads();
    if (tid < 128 && row0 + tid < Nn) {
        g_asrc[row0 + tid] = s_ua[tid];
        g_adst[row0 + tid] = s_ud[tid];
    }
}

// ---------------- softmax aggregation (R11 form): one warp per dst ----------------
// fast path for deg<=32 (one batch): pass-1 values kept in registers.
__global__ void k_aggregate(const float* __restrict__ bias, float* __restrict__ outp,
                            int N, int write_final) {
    int warp = (blockIdx.x * blockDim.x + threadIdx.x) >> 5;
    int lane = threadIdx.x & 31;
    if (warp >= N) return;

    int beg = g_rowptr[warp];
    int end = g_rowptr[warp + 1];
    float ad = g_adst[warp];

    float4 acc = make_float4(0.f, 0.f, 0.f, 0.f);
    float denom = 0.f;

    if (end - beg <= 32) {
        // single batch: one gather of (srcs, asrc), no second pass
        int e = beg + lane;
        int s = 0;
        float v = -1e30f;
        if (e < end) {
            s = __ldg(&g_srcs[e]);
            float t = __ldg(&g_asrc[s]) + ad;
            v = t > 0.f ? t : 0.2f * t;
        }
        float m = v;
#pragma unroll
        for (int off = 16; off; off >>= 1)
            m = fmaxf(m, __shfl_xor_sync(0xffffffffu, m, off));
        float w = __expf(v - m);      // invalid lanes: exp(-huge) = 0
        denom = w;
        int cnt = end - beg;
        for (int i = 0; i < cnt; i++) {
            float wi = __shfl_sync(0xffffffffu, w, i);
            int   si = __shfl_sync(0xffffffffu, s, i);
            uint2 raw = __ldg((const uint2*)&g_h[(size_t)si * 128 + lane * 4]);
            __half2 h01 = *reinterpret_cast<__half2*>(&raw.x);
            __half2 h23 = *reinterpret_cast<__half2*>(&raw.y);
            float2 f01 = __half22float2(h01);
            float2 f23 = __half22float2(h23);
            acc.x += wi * f01.x; acc.y += wi * f01.y;
            acc.z += wi * f23.x; acc.w += wi * f23.y;
        }
    } else {
        // pass 1: segment max
        float m = -1e30f;
        for (int e = beg + lane; e < end; e += 32) {
            int s = __ldg(&g_srcs[e]);
            float v = __ldg(&g_asrc[s]) + ad;
            v = v > 0.f ? v : 0.2f * v;
            m = fmaxf(m, v);
        }
#pragma unroll
        for (int off = 16; off; off >>= 1)
            m = fmaxf(m, __shfl_xor_sync(0xffffffffu, m, off));
        // pass 2
        for (int base = beg; base < end; base += 32) {
            int e = base + lane;
            float w = 0.f;
            int s = 0;
            if (e < end) {
                s = __ldg(&g_srcs[e]);
                float v = __ldg(&g_asrc[s]) + ad;
                v = v > 0.f ? v : 0.2f * v;
                w = __expf(v - m);
            }
            denom += w;
            int cnt = min(32, end - base);
            for (int i = 0; i < cnt; i++) {
                float wi = __shfl_sync(0xffffffffu, w, i);
                int   si = __shfl_sync(0xffffffffu, s, i);
                uint2 raw = __ldg((const uint2*)&g_h[(size_t)si * 128 + lane * 4]);
                __half2 h01 = *reinterpret_cast<__half2*>(&raw.x);
                __half2 h23 = *reinterpret_cast<__half2*>(&raw.y);
                float2 f01 = __half22float2(h01);
                float2 f23 = __half22float2(h23);
                acc.x += wi * f01.x; acc.y += wi * f01.y;
                acc.z += wi * f23.x; acc.w += wi * f23.y;
            }
        }
    }
#pragma unroll
    for (int off = 16; off; off >>= 1)
        denom += __shfl_xor_sync(0xffffffffu, denom, off);

    float inv = 1.f / denom;
    float4 bv = *(const float4*)&bias[lane * 4];
    float4 r;
    r.x = acc.x * inv + bv.x;
    r.y = acc.y * inv + bv.y;
    r.z = acc.z * inv + bv.z;
    r.w = acc.w * inv + bv.w;
    if (write_final) {
        *(float4*)&outp[(size_t)warp * 128 + lane * 4] = r;
    } else {
        r.x = r.x > 0.f ? r.x : expm1f(r.x);
        r.y = r.y > 0.f ? r.y : expm1f(r.y);
        r.z = r.z > 0.f ? r.z : expm1f(r.z);
        r.w = r.w > 0.f ? r.w : expm1f(r.w);
        size_t idx = (size_t)warp * 128 + lane * 4;
        split4_store(r, &g_xh[idx], &g_xl[idx]);
    }
}

// ---------------- launch ----------------
extern "C" void kernel_launch(void* const* d_in, const int* in_sizes, int n_in,
                              void* d_out, int out_size) {
    const float* x  = (const float*)d_in[0];
    const int*   ei = (const int*)d_in[1];
    int N  = in_sizes[0] / F;
    int E  = in_sizes[1] / 2;
    int ET = E + N;
    int nb = (N + 1023) / 1024;

    static int smem_set = 0;
    if (!smem_set) {
        cudaFuncSetAttribute(k_gemm_mma, cudaFuncAttributeMaxDynamicSharedMemorySize, GEMM_SMEM);
        smem_set = 1;
    }

    int warp_blocks = (N * 32 + 255) / 256;
    int gemm_blocks = (N + 127) / 128;

    // launch #4 = k_gemm_mma (ncu captures the 4th launch)
    k_split_x<<<(N * 32 + 255) / 256, 256>>>(x, N * 32);
    k_prepW_all<<<48, 256>>>((const float*)d_in[2], (const float*)d_in[6], (const float*)d_in[10]);
    k_zero_deg<<<(N + 255) / 256, 256>>>(N);
    k_gemm_mma<<<gemm_blocks, 512, GEMM_SMEM>>>(0, (const float*)d_in[3], (const float*)d_in[4], N);
    k_count<<<(ET + 255) / 256, 256>>>(ei, E, N);
    k_scan1<<<nb, 256>>>(N);
    k_scan2<<<1, 256>>>(nb);
    k_scan3<<<nb, 256>>>(N, nb);
    k_scatter<<<(ET + 255) / 256, 256>>>(ei, E, N);

    for (int l = 0; l < 3; l++) {
        const float* as = (const float*)d_in[3 + 4 * l];
        const float* ad = (const float*)d_in[4 + 4 * l];
        const float* b  = (const float*)d_in[5 + 4 * l];
        if (l > 0)
            k_gemm_mma<<<gemm_blocks, 512, GEMM_SMEM>>>(l, as, ad, N);
        k_aggregate<<<warp_blocks, 256>>>(b, l == 2 ? (float*)d_out : nullptr, N, l == 2 ? 1 : 0);
    }
}

// round 13
// speedup vs baseline: 1.1329x; 1.0399x over previous
#include <cuda_runtime.h>
#include <cuda_bf16.h>
#include <cuda_fp16.h>
#include <stdint.h>

#define F 128
#define NMAX 100000
#define EMAX 1700000   // E + N self loops

// ---------------- scratch (alloc-free: __device__ globals) ----------------
__device__ __half g_h[NMAX * F];                // transformed features h = feat @ W (fp16)
__device__ __nv_bfloat16 g_xh[NMAX * F];        // current layer input, bf16 hi
__device__ __nv_bfloat16 g_xl[NMAX * F];        // current layer input, bf16 lo
__device__ __nv_bfloat16 g_wh[3][F * F];        // W bf16 hi per layer
__device__ __nv_bfloat16 g_wl[3][F * F];        // W bf16 lo per layer
__device__ float g_asrc[NMAX];
__device__ float g_adst[NMAX];
__device__ int   g_deg[NMAX];
__device__ int   g_rowptr[NMAX + 1];
__device__ int   g_cursor[NMAX];
__device__ int   g_srcs[EMAX];                  // src indices sorted by dst (CSR)
__device__ int   g_bsum[256];                   // scan block sums
__device__ int   g_bpre[257];                   // scan block prefixes (+ total)

// ---------------- helpers ----------------
__device__ __forceinline__ uint32_t smem_u32(const void* p) {
    uint32_t a;
    asm("{ .reg .u64 t; cvta.to.shared.u64 t, %1; cvt.u32.u64 %0, t; }" : "=r"(a) : "l"(p));
    return a;
}
__device__ __forceinline__ void ldsm_x4(uint32_t* r, uint32_t addr) {
    asm volatile("ldmatrix.sync.aligned.m8n8.x4.shared.b16 {%0,%1,%2,%3}, [%4];"
                 : "=r"(r[0]), "=r"(r[1]), "=r"(r[2]), "=r"(r[3]) : "r"(addr));
}
__device__ __forceinline__ void ldsm_x4_t(uint32_t* r, uint32_t addr) {
    asm volatile("ldmatrix.sync.aligned.m8n8.x4.trans.shared.b16 {%0,%1,%2,%3}, [%4];"
                 : "=r"(r[0]), "=r"(r[1]), "=r"(r[2]), "=r"(r[3]) : "r"(addr));
}
__device__ __forceinline__ void mma_bf16(float* c, const uint32_t* a, const uint32_t* b) {
    asm volatile("mma.sync.aligned.m16n8k16.row.col.f32.bf16.bf16.f32 "
                 "{%0,%1,%2,%3}, {%4,%5,%6,%7}, {%8,%9}, {%0,%1,%2,%3};"
                 : "+f"(c[0]), "+f"(c[1]), "+f"(c[2]), "+f"(c[3])
                 : "r"(a[0]), "r"(a[1]), "r"(a[2]), "r"(a[3]), "r"(b[0]), "r"(b[1]));
}
#define CP_ASYNC16(dst, src) \
    asm volatile("cp.async.cg.shared.global [%0], [%1], 16;" :: "r"(dst), "l"(src) : "memory")
#define CP_COMMIT()   asm volatile("cp.async.commit_group;" ::: "memory")
#define CP_WAIT1()    asm volatile("cp.async.wait_group 1;" ::: "memory")

__device__ __forceinline__ void split_bf16(float x, __nv_bfloat16& h, __nv_bfloat16& l) {
    h = __float2bfloat16_rn(x);
    l = __float2bfloat16_rn(x - __bfloat162float(h));
}
__device__ __forceinline__ void split4_store(float4 r, __nv_bfloat16* ph, __nv_bfloat16* pl) {
    __nv_bfloat16 h0, l0, h1, l1, h2, l2, h3, l3;
    split_bf16(r.x, h0, l0); split_bf16(r.y, h1, l1);
    split_bf16(r.z, h2, l2); split_bf16(r.w, h3, l3);
    uint2 hp, lp;
    hp.x = (uint32_t)__bfloat16_as_ushort(h0) | ((uint32_t)__bfloat16_as_ushort(h1) << 16);
    hp.y = (uint32_t)__bfloat16_as_ushort(h2) | ((uint32_t)__bfloat16_as_ushort(h3) << 16);
    lp.x = (uint32_t)__bfloat16_as_ushort(l0) | ((uint32_t)__bfloat16_as_ushort(l1) << 16);
    lp.y = (uint32_t)__bfloat16_as_ushort(l2) | ((uint32_t)__bfloat16_as_ushort(l3) << 16);
    *(uint2*)ph = hp;
    *(uint2*)pl = lp;
}

// ---------------- input / weight splitting ----------------
__global__ void k_split_x(const float* __restrict__ x, int total4) {
    int i = blockIdx.x * blockDim.x + threadIdx.x;
    if (i >= total4) return;
    float4 v = ((const float4*)x)[i];
    split4_store(v, &g_xh[i * 4], &g_xl[i * 4]);
}
__global__ void k_prepW_all(const float* __restrict__ W0, const float* __restrict__ W1,
                            const float* __restrict__ W2) {
    int i = blockIdx.x * blockDim.x + threadIdx.x;
    if (i >= 3 * 4096) return;
    int l = i >> 12, j = i & 4095;
    const float* W = (l == 0) ? W0 : (l == 1) ? W1 : W2;
    float4 v = ((const float4*)W)[j];
    split4_store(v, &g_wh[l][j * 4], &g_wl[l][j * 4]);
}

// ---------------- CSR build ----------------
__global__ void k_zero_deg(int N) {
    int i = blockIdx.x * blockDim.x + threadIdx.x;
    if (i < N) g_deg[i] = 0;
}
__global__ void k_count(const int* __restrict__ ei, int E, int N) {
    int j = blockIdx.x * blockDim.x + threadIdx.x;
    if (j >= E + N) return;
    int d = (j < E) ? ei[E + j] : (j - E);
    atomicAdd(&g_deg[d], 1);
}
__global__ void k_scan1(int N) {
    __shared__ int s[256];
    int t = threadIdx.x, b = blockIdx.x;
    int i0 = b * 1024 + t * 4;
    int sum = 0;
#pragma unroll
    for (int j = 0; j < 4; j++)
        if (i0 + j < N) sum += g_deg[i0 + j];
    s[t] = sum;
    __syncthreads();
#pragma unroll
    for (int off = 128; off; off >>= 1) {
        if (t < off) s[t] += s[t + off];
        __syncthreads();
    }
    if (t == 0) g_bsum[b] = s[0];
}
__global__ void k_scan2(int nb) {
    __shared__ int s[256];
    int t = threadIdx.x;
    int v = (t < nb) ? g_bsum[t] : 0;
    s[t] = v;
    __syncthreads();
#pragma unroll
    for (int off = 1; off < 256; off <<= 1) {
        int u = (t >= off) ? s[t - off] : 0;
        __syncthreads();
        s[t] += u;
        __syncthreads();
    }
    if (t <= nb) g_bpre[t] = (t == 0) ? 0 : s[t - 1];
    if (t == 255) g_bpre[256] = s[255];
}
__global__ void k_scan3(int N, int nb) {
    __shared__ int s[256];
    int t = threadIdx.x, b = blockIdx.x;
    int i0 = b * 1024 + t * 4;
    int d[4];
    int sum = 0;
#pragma unroll
    for (int j = 0; j < 4; j++) {
        d[j] = (i0 + j < N) ? g_deg[i0 + j] : 0;
        sum += d[j];
    }
    s[t] = sum;
    __syncthreads();
#pragma unroll
    for (int off = 1; off < 256; off <<= 1) {
        int u = (t >= off) ? s[t - off] : 0;
        __syncthreads();
        s[t] += u;
        __syncthreads();
    }
    int run = g_bpre[b] + s[t] - sum;
#pragma unroll
    for (int j = 0; j < 4; j++) {
        if (i0 + j < N) {
            g_rowptr[i0 + j] = run;
            g_cursor[i0 + j] = run;
        }
        run += d[j];
    }
    if (b == 0 && t == 0) g_rowptr[N] = g_bpre[nb];
}
__global__ void k_scatter(const int* __restrict__ ei, int E, int N) {
    int j = blockIdx.x * blockDim.x + threadIdx.x;
    if (j >= E + N) return;
    int sIdx, d;
    if (j < E) { sIdx = ei[j]; d = ei[E + j]; }
    else       { sIdx = j - E; d = j - E; }
    int pos = atomicAdd(&g_cursor[d], 1);
    g_srcs[pos] = sIdx;
}

// ---------------- persistent bf16x3 tensor-core GEMM, cp.async double-buffered A ----
// grid=148, 512 threads, 16 warps 4(M)x4(N), warp tile 32x32. B staged once/CTA.
#define AS_STRIDE 136
#define TILE_B (128 * AS_STRIDE * 2)     // 34816 bytes per 128x128 bf16 image
#define OFF_BH 0
#define OFF_BL (TILE_B)
#define OFF_A0 (2 * TILE_B)              // buf0: Ah at +0, Al at +TILE_B
#define OFF_A1 (4 * TILE_B)              // buf1
#define OFF_SAS (6 * TILE_B)
#define OFF_SAD (OFF_SAS + 512)
#define OFF_SUA (OFF_SAD + 512)
#define OFF_SUD (OFF_SUA + 512)
#define GEMM_SMEM (OFF_SUD + 512)        // 210944 bytes

__device__ __forceinline__ void prefetchA(int t, uint32_t abuf, int Nn) {
    int tid = threadIdx.x;
    int r = tid >> 2, seg = (tid & 3) * 32;
    int gr = min(t * 128 + r, Nn - 1);
    const char* sh = (const char*)&g_xh[(size_t)gr * 128 + seg];
    const char* sl = (const char*)&g_xl[(size_t)gr * 128 + seg];
    uint32_t dh = abuf + (uint32_t)(r * AS_STRIDE + seg) * 2;
    uint32_t dl = dh + TILE_B;
#pragma unroll
    for (int j = 0; j < 4; j++) {
        CP_ASYNC16(dh + j * 16, sh + j * 16);
        CP_ASYNC16(dl + j * 16, sl + j * 16);
    }
}

__global__ void __launch_bounds__(512)
k_gemm_mma(int layer, const float* __restrict__ av_s, const float* __restrict__ av_d,
           int Nn, int ntiles) {
    extern __shared__ char smem[];
    const uint32_t sb = smem_u32(smem);
    const int tid = threadIdx.x, lane = tid & 31, wid = tid >> 5;

    float* s_as = (float*)(smem + OFF_SAS);
    float* s_ad = (float*)(smem + OFF_SAD);
    float* s_ua = (float*)(smem + OFF_SUA);
    float* s_ud = (float*)(smem + OFF_SUD);
    if (tid < 128) {
        s_as[tid] = av_s[tid];
        s_ad[tid] = av_d[tid];
    }

    {   // stage B once: 128 rows, 4 threads/row, 32 bf16 (4 uint4) per image
        int r = tid >> 2, seg = (tid & 3) * 32;
        const uint4* sBh = (const uint4*)&g_wh[layer][r * 128 + seg];
        const uint4* sBl = (const uint4*)&g_wl[layer][r * 128 + seg];
        uint4* dBh = (uint4*)((__nv_bfloat16*)(smem + OFF_BH) + r * AS_STRIDE + seg);
        uint4* dBl = (uint4*)((__nv_bfloat16*)(smem + OFF_BL) + r * AS_STRIDE + seg);
#pragma unroll
        for (int j = 0; j < 4; j++) {
            dBh[j] = sBh[j];
            dBl[j] = sBl[j];
        }
    }

    const int wm = wid & 3, wn = wid >> 2;
    const int wrow = wm * 32, wcol = wn * 32;
    const int lr = lane & 15, lc = lane >> 4;

    int t = blockIdx.x;
    prefetchA(t, sb + OFF_A0, Nn);
    CP_COMMIT();
    int buf = 0;

    for (; t < ntiles; t += gridDim.x) {
        int tn = t + gridDim.x;
        if (tn < ntiles) prefetchA(tn, sb + (buf ? OFF_A0 : OFF_A1), Nn);
        CP_COMMIT();
        CP_WAIT1();              // A(t) landed (and B on first iter)
        __syncthreads();
        if (tid < 128) { s_ua[tid] = 0.f; s_ud[tid] = 0.f; }

        const uint32_t abase = sb + (buf ? OFF_A1 : OFF_A0);
        float acc[2][4][4];
#pragma unroll
        for (int i = 0; i < 2; i++)
#pragma unroll
            for (int j = 0; j < 4; j++)
#pragma unroll
                for (int q = 0; q < 4; q++) acc[i][j][q] = 0.f;

#pragma unroll
        for (int pass = 0; pass < 3; pass++) {
            uint32_t aoff = abase + ((pass == 1) ? TILE_B : 0);
            uint32_t boff = sb + ((pass == 2) ? OFF_BL : OFF_BH);
#pragma unroll
            for (int ks = 0; ks < 8; ks++) {
                int k0 = ks * 16;
                uint32_t a[2][4], b[2][4];
#pragma unroll
                for (int mt = 0; mt < 2; mt++)
                    ldsm_x4(a[mt], aoff + ((wrow + mt * 16 + lr) * AS_STRIDE + lc * 8 + k0) * 2);
#pragma unroll
                for (int ng = 0; ng < 2; ng++)
                    ldsm_x4_t(b[ng], boff + ((k0 + lr) * AS_STRIDE + wcol + ng * 16 + lc * 8) * 2);
#pragma unroll
                for (int mt = 0; mt < 2; mt++)
#pragma unroll
                    for (int nt = 0; nt < 4; nt++)
                        mma_bf16(acc[mt][nt], a[mt], &b[nt >> 1][(nt & 1) * 2]);
            }
        }

        const int row0 = t * 128;
        float pa[4] = {0.f, 0.f, 0.f, 0.f}, pd[4] = {0.f, 0.f, 0.f, 0.f};
#pragma unroll
        for (int mt = 0; mt < 2; mt++) {
#pragma unroll
            for (int half = 0; half < 2; half++) {
                int rl = wrow + mt * 16 + half * 8 + (lane >> 2);
                int gr = row0 + rl;
                bool ok = gr < Nn;
#pragma unroll
                for (int nt = 0; nt < 4; nt++) {
                    int cl = wcol + nt * 8 + (lane & 3) * 2;
                    float v0 = acc[mt][nt][half * 2 + 0];
                    float v1 = acc[mt][nt][half * 2 + 1];
                    if (ok) *(__half2*)&g_h[(size_t)gr * 128 + cl] = __floats2half2_rn(v0, v1);
                    pa[mt * 2 + half] += v0 * s_as[cl] + v1 * s_as[cl + 1];
                    pd[mt * 2 + half] += v0 * s_ad[cl] + v1 * s_ad[cl + 1];
                }
            }
        }
        __syncthreads();   // s_ua/s_ud zero visible; all compute reads of A(buf) done
#pragma unroll
        for (int i = 0; i < 4; i++) {
            int rl = wrow + (i >> 1) * 16 + (i & 1) * 8 + (lane >> 2);
            atomicAdd(&s_ua[rl], pa[i]);
            atomicAdd(&s_ud[rl], pd[i]);
        }
        __syncthreads();
        if (tid < 128 && row0 + tid < Nn) {
            g_asrc[row0 + tid] = s_ua[tid];
            g_adst[row0 + tid] = s_ud[tid];
        }
        buf ^= 1;
    }
}

// ---------------- softmax aggregation: one warp per dst; deg<=32 fast path ----------
__global__ void k_aggregate(const float* __restrict__ bias, float* __restrict__ outp,
                            int N, int write_final) {
    int warp = (blockIdx.x * blockDim.x + threadIdx.x) >> 5;
    int lane = threadIdx.x & 31;
    if (warp >= N) return;

    int beg = g_rowptr[warp];
    int end = g_rowptr[warp + 1];
    float ad = g_adst[warp];

    float4 acc = make_float4(0.f, 0.f, 0.f, 0.f);
    float denom = 0.f;

    if (end - beg <= 32) {
        int e = beg + lane;
        int s = 0;
        float v = -1e30f;
        if (e < end) {
            s = __ldg(&g_srcs[e]);
            float t = __ldg(&g_asrc[s]) + ad;
            v = t > 0.f ? t : 0.2f * t;
        }
        float m = v;
#pragma unroll
        for (int off = 16; off; off >>= 1)
            m = fmaxf(m, __shfl_xor_sync(0xffffffffu, m, off));
        float w = __expf(v - m);
        denom = w;
        int cnt = end - beg;
        for (int i = 0; i < cnt; i++) {
            float wi = __shfl_sync(0xffffffffu, w, i);
            int   si = __shfl_sync(0xffffffffu, s, i);
            uint2 raw = __ldg((const uint2*)&g_h[(size_t)si * 128 + lane * 4]);
            __half2 h01 = *reinterpret_cast<__half2*>(&raw.x);
            __half2 h23 = *reinterpret_cast<__half2*>(&raw.y);
            float2 f01 = __half22float2(h01);
            float2 f23 = __half22float2(h23);
            acc.x += wi * f01.x; acc.y += wi * f01.y;
            acc.z += wi * f23.x; acc.w += wi * f23.y;
        }
    } else {
        float m = -1e30f;
        for (int e = beg + lane; e < end; e += 32) {
            int s = __ldg(&g_srcs[e]);
            float v = __ldg(&g_asrc[s]) + ad;
            v = v > 0.f ? v : 0.2f * v;
            m = fmaxf(m, v);
        }
#pragma unroll
        for (int off = 16; off; off >>= 1)
            m = fmaxf(m, __shfl_xor_sync(0xffffffffu, m, off));
        for (int base = beg; base < end; base += 32) {
            int e = base + lane;
            float w = 0.f;
            int s = 0;
            if (e < end) {
                s = __ldg(&g_srcs[e]);
                float v = __ldg(&g_asrc[s]) + ad;
                v = v > 0.f ? v : 0.2f * v;
                w = __expf(v - m);
            }
            denom += w;
            int cnt = min(32, end - base);
            for (int i = 0; i < cnt; i++) {
                float wi = __shfl_sync(0xffffffffu, w, i);
                int   si = __shfl_sync(0xffffffffu, s, i);
                uint2 raw = __ldg((const uint2*)&g_h[(size_t)si * 128 + lane * 4]);
                __half2 h01 = *reinterpret_cast<__half2*>(&raw.x);
                __half2 h23 = *reinterpret_cast<__half2*>(&raw.y);
                float2 f01 = __half22float2(h01);
                float2 f23 = __half22float2(h23);
                acc.x += wi * f01.x; acc.y += wi * f01.y;
                acc.z += wi * f23.x; acc.w += wi * f23.y;
            }
        }
    }
#pragma unroll
    for (int off = 16; off; off >>= 1)
        denom += __shfl_xor_sync(0xffffffffu, denom, off);

    float inv = 1.f / denom;
    float4 bv = *(const float4*)&bias[lane * 4];
    float4 r;
    r.x = acc.x * inv + bv.x;
    r.y = acc.y * inv + bv.y;
    r.z = acc.z * inv + bv.z;
    r.w = acc.w * inv + bv.w;
    if (write_final) {
        *(float4*)&outp[(size_t)warp * 128 + lane * 4] = r;
    } else {
        r.x = r.x > 0.f ? r.x : expm1f(r.x);
        r.y = r.y > 0.f ? r.y : expm1f(r.y);
        r.z = r.z > 0.f ? r.z : expm1f(r.z);
        r.w = r.w > 0.f ? r.w : expm1f(r.w);
        size_t idx = (size_t)warp * 128 + lane * 4;
        split4_store(r, &g_xh[idx], &g_xl[idx]);
    }
}

// ---------------- launch ----------------
extern "C" void kernel_launch(void* const* d_in, const int* in_sizes, int n_in,
                              void* d_out, int out_size) {
    const float* x  = (const float*)d_in[0];
    const int*   ei = (const int*)d_in[1];
    int N  = in_sizes[0] / F;
    int E  = in_sizes[1] / 2;
    int ET = E + N;
    int nb = (N + 1023) / 1024;
    int ntiles = (N + 127) / 128;

    static int smem_set = 0;
    if (!smem_set) {
        cudaFuncSetAttribute(k_gemm_mma, cudaFuncAttributeMaxDynamicSharedMemorySize, GEMM_SMEM);
        smem_set = 1;
    }

    int warp_blocks = (N * 32 + 255) / 256;

    // launch #4 = k_gemm_mma (ncu captures the 4th launch)
    k_split_x<<<(N * 32 + 255) / 256, 256>>>(x, N * 32);
    k_prepW_all<<<48, 256>>>((const float*)d_in[2], (const float*)d_in[6], (const float*)d_in[10]);
    k_zero_deg<<<(N + 255) / 256, 256>>>(N);
    k_gemm_mma<<<148, 512, GEMM_SMEM>>>(0, (const float*)d_in[3], (const float*)d_in[4], N, ntiles);
    k_count<<<(ET + 255) / 256, 256>>>(ei, E, N);
    k_scan1<<<nb, 256>>>(N);
    k_scan2<<<1, 256>>>(nb);
    k_scan3<<<nb, 256>>>(N, nb);
    k_scatter<<<(ET + 255) / 256, 256>>>(ei, E, N);

    for (int l = 0; l < 3; l++) {
        const float* as = (const float*)d_in[3 + 4 * l];
        const float* ad = (const float*)d_in[4 + 4 * l];
        const float* b  = (const float*)d_in[5 + 4 * l];
        if (l > 0)
            k_gemm_mma<<<148, 512, GEMM_SMEM>>>(l, as, ad, N, ntiles);
        k_aggregate<<<warp_blocks, 256>>>(b, l == 2 ? (float*)d_out : nullptr, N, l == 2 ? 1 : 0);
    }
}

// round 14
// speedup vs baseline: 1.1627x; 1.0263x over previous
#include <cuda_runtime.h>
#include <cuda_bf16.h>
#include <cuda_fp16.h>
#include <stdint.h>

#define F 128
#define NMAX 100000
#define EMAX 1700000   // E + N self loops

// ---------------- scratch (alloc-free: __device__ globals) ----------------
__device__ __half g_h[NMAX * F];                // transformed features h = feat @ W (fp16)
__device__ __nv_bfloat16 g_xh[NMAX * F];        // current layer input, bf16 hi
__device__ __nv_bfloat16 g_xl[NMAX * F];        // current layer input, bf16 lo
__device__ __nv_bfloat16 g_wh[3][F * F];        // W bf16 hi per layer
__device__ __nv_bfloat16 g_wl[3][F * F];        // W bf16 lo per layer
__device__ float g_asrc[NMAX];
__device__ float g_adst[NMAX];
__device__ int   g_deg[NMAX];
__device__ int   g_rowptr[NMAX + 1];
__device__ int   g_cursor[NMAX];
__device__ int   g_srcs[EMAX];                  // src indices sorted by dst (CSR)
__device__ int   g_bsum[256];                   // scan block sums
__device__ int   g_bpre[257];                   // scan block prefixes (+ total)

// ---------------- helpers ----------------
__device__ __forceinline__ uint32_t smem_u32(const void* p) {
    uint32_t a;
    asm("{ .reg .u64 t; cvta.to.shared.u64 t, %1; cvt.u32.u64 %0, t; }" : "=r"(a) : "l"(p));
    return a;
}
__device__ __forceinline__ void ldsm_x4(uint32_t* r, uint32_t addr) {
    asm volatile("ldmatrix.sync.aligned.m8n8.x4.shared.b16 {%0,%1,%2,%3}, [%4];"
                 : "=r"(r[0]), "=r"(r[1]), "=r"(r[2]), "=r"(r[3]) : "r"(addr));
}
__device__ __forceinline__ void ldsm_x4_t(uint32_t* r, uint32_t addr) {
    asm volatile("ldmatrix.sync.aligned.m8n8.x4.trans.shared.b16 {%0,%1,%2,%3}, [%4];"
                 : "=r"(r[0]), "=r"(r[1]), "=r"(r[2]), "=r"(r[3]) : "r"(addr));
}
__device__ __forceinline__ void mma_bf16(float* c, const uint32_t* a, const uint32_t* b) {
    asm volatile("mma.sync.aligned.m16n8k16.row.col.f32.bf16.bf16.f32 "
                 "{%0,%1,%2,%3}, {%4,%5,%6,%7}, {%8,%9}, {%0,%1,%2,%3};"
                 : "+f"(c[0]), "+f"(c[1]), "+f"(c[2]), "+f"(c[3])
                 : "r"(a[0]), "r"(a[1]), "r"(a[2]), "r"(a[3]), "r"(b[0]), "r"(b[1]));
}
#define CP_ASYNC16(dst, src) \
    asm volatile("cp.async.cg.shared.global [%0], [%1], 16;" :: "r"(dst), "l"(src) : "memory")
#define CP_COMMIT()   asm volatile("cp.async.commit_group;" ::: "memory")
#define CP_WAIT1()    asm volatile("cp.async.wait_group 1;" ::: "memory")

__device__ __forceinline__ void split_bf16(float x, __nv_bfloat16& h, __nv_bfloat16& l) {
    h = __float2bfloat16_rn(x);
    l = __float2bfloat16_rn(x - __bfloat162float(h));
}
__device__ __forceinline__ void split4_store(float4 r, __nv_bfloat16* ph, __nv_bfloat16* pl) {
    __nv_bfloat16 h0, l0, h1, l1, h2, l2, h3, l3;
    split_bf16(r.x, h0, l0); split_bf16(r.y, h1, l1);
    split_bf16(r.z, h2, l2); split_bf16(r.w, h3, l3);
    uint2 hp, lp;
    hp.x = (uint32_t)__bfloat16_as_ushort(h0) | ((uint32_t)__bfloat16_as_ushort(h1) << 16);
    hp.y = (uint32_t)__bfloat16_as_ushort(h2) | ((uint32_t)__bfloat16_as_ushort(h3) << 16);
    lp.x = (uint32_t)__bfloat16_as_ushort(l0) | ((uint32_t)__bfloat16_as_ushort(l1) << 16);
    lp.y = (uint32_t)__bfloat16_as_ushort(l2) | ((uint32_t)__bfloat16_as_ushort(l3) << 16);
    *(uint2*)ph = hp;
    *(uint2*)pl = lp;
}

// ---------------- input / weight splitting ----------------
__global__ void k_split_x(const float* __restrict__ x, int total4) {
    int i = blockIdx.x * blockDim.x + threadIdx.x;
    if (i >= total4) return;
    float4 v = ((const float4*)x)[i];
    split4_store(v, &g_xh[i * 4], &g_xl[i * 4]);
}
__global__ void k_prepW_all(const float* __restrict__ W0, const float* __restrict__ W1,
                            const float* __restrict__ W2) {
    int i = blockIdx.x * blockDim.x + threadIdx.x;
    if (i >= 3 * 4096) return;
    int l = i >> 12, j = i & 4095;
    const float* W = (l == 0) ? W0 : (l == 1) ? W1 : W2;
    float4 v = ((const float4*)W)[j];
    split4_store(v, &g_wh[l][j * 4], &g_wl[l][j * 4]);
}

// ---------------- CSR build ----------------
__global__ void k_zero_deg(int N) {
    int i = blockIdx.x * blockDim.x + threadIdx.x;
    if (i < N) g_deg[i] = 0;
}
__global__ void k_count(const int* __restrict__ ei, int E, int N) {
    int j = blockIdx.x * blockDim.x + threadIdx.x;
    if (j >= E + N) return;
    int d = (j < E) ? ei[E + j] : (j - E);
    atomicAdd(&g_deg[d], 1);
}
__global__ void k_scan1(int N) {
    __shared__ int s[256];
    int t = threadIdx.x, b = blockIdx.x;
    int i0 = b * 1024 + t * 4;
    int sum = 0;
#pragma unroll
    for (int j = 0; j < 4; j++)
        if (i0 + j < N) sum += g_deg[i0 + j];
    s[t] = sum;
    __syncthreads();
#pragma unroll
    for (int off = 128; off; off >>= 1) {
        if (t < off) s[t] += s[t + off];
        __syncthreads();
    }
    if (t == 0) g_bsum[b] = s[0];
}
__global__ void k_scan2(int nb) {
    __shared__ int s[256];
    int t = threadIdx.x;
    int v = (t < nb) ? g_bsum[t] : 0;
    s[t] = v;
    __syncthreads();
#pragma unroll
    for (int off = 1; off < 256; off <<= 1) {
        int u = (t >= off) ? s[t - off] : 0;
        __syncthreads();
        s[t] += u;
        __syncthreads();
    }
    if (t <= nb) g_bpre[t] = (t == 0) ? 0 : s[t - 1];
    if (t == 255) g_bpre[256] = s[255];
}
__global__ void k_scan3(int N, int nb) {
    __shared__ int s[256];
    int t = threadIdx.x, b = blockIdx.x;
    int i0 = b * 1024 + t * 4;
    int d[4];
    int sum = 0;
#pragma unroll
    for (int j = 0; j < 4; j++) {
        d[j] = (i0 + j < N) ? g_deg[i0 + j] : 0;
        sum += d[j];
    }
    s[t] = sum;
    __syncthreads();
#pragma unroll
    for (int off = 1; off < 256; off <<= 1) {
        int u = (t >= off) ? s[t - off] : 0;
        __syncthreads();
        s[t] += u;
        __syncthreads();
    }
    int run = g_bpre[b] + s[t] - sum;
#pragma unroll
    for (int j = 0; j < 4; j++) {
        if (i0 + j < N) {
            g_rowptr[i0 + j] = run;
            g_cursor[i0 + j] = run;
        }
        run += d[j];
    }
    if (b == 0 && t == 0) g_rowptr[N] = g_bpre[nb];
}
__global__ void k_scatter(const int* __restrict__ ei, int E, int N) {
    int j = blockIdx.x * blockDim.x + threadIdx.x;
    if (j >= E + N) return;
    int sIdx, d;
    if (j < E) { sIdx = ei[j]; d = ei[E + j]; }
    else       { sIdx = j - E; d = j - E; }
    int pos = atomicAdd(&g_cursor[d], 1);
    g_srcs[pos] = sIdx;
}

// ---------------- persistent bf16x3 tensor-core GEMM, cp.async double-buffered A ----
#define AS_STRIDE 136
#define TILE_B (128 * AS_STRIDE * 2)     // 34816 bytes per 128x128 bf16 image
#define OFF_BH 0
#define OFF_BL (TILE_B)
#define OFF_A0 (2 * TILE_B)              // buf0: Ah at +0, Al at +TILE_B
#define OFF_A1 (4 * TILE_B)              // buf1
#define OFF_SAS (6 * TILE_B)
#define OFF_SAD (OFF_SAS + 512)
#define OFF_SUA (OFF_SAD + 512)
#define OFF_SUD (OFF_SUA + 512)
#define GEMM_SMEM (OFF_SUD + 512)        // 210944 bytes

__device__ __forceinline__ void prefetchA(int t, uint32_t abuf, int Nn) {
    int tid = threadIdx.x;
    int r = tid >> 2, seg = (tid & 3) * 32;
    int gr = min(t * 128 + r, Nn - 1);
    const char* sh = (const char*)&g_xh[(size_t)gr * 128 + seg];
    const char* sl = (const char*)&g_xl[(size_t)gr * 128 + seg];
    uint32_t dh = abuf + (uint32_t)(r * AS_STRIDE + seg) * 2;
    uint32_t dl = dh + TILE_B;
#pragma unroll
    for (int j = 0; j < 4; j++) {
        CP_ASYNC16(dh + j * 16, sh + j * 16);
        CP_ASYNC16(dl + j * 16, sl + j * 16);
    }
}

__global__ void __launch_bounds__(512)
k_gemm_mma(int layer, const float* __restrict__ av_s, const float* __restrict__ av_d,
           int Nn, int ntiles) {
    extern __shared__ char smem[];
    const uint32_t sb = smem_u32(smem);
    const int tid = threadIdx.x, lane = tid & 31, wid = tid >> 5;

    float* s_as = (float*)(smem + OFF_SAS);
    float* s_ad = (float*)(smem + OFF_SAD);
    float* s_ua = (float*)(smem + OFF_SUA);
    float* s_ud = (float*)(smem + OFF_SUD);
    if (tid < 128) {
        s_as[tid] = av_s[tid];
        s_ad[tid] = av_d[tid];
    }

    {   // stage B once: 128 rows, 4 threads/row, 32 bf16 (4 uint4) per image
        int r = tid >> 2, seg = (tid & 3) * 32;
        const uint4* sBh = (const uint4*)&g_wh[layer][r * 128 + seg];
        const uint4* sBl = (const uint4*)&g_wl[layer][r * 128 + seg];
        uint4* dBh = (uint4*)((__nv_bfloat16*)(smem + OFF_BH) + r * AS_STRIDE + seg);
        uint4* dBl = (uint4*)((__nv_bfloat16*)(smem + OFF_BL) + r * AS_STRIDE + seg);
#pragma unroll
        for (int j = 0; j < 4; j++) {
            dBh[j] = sBh[j];
            dBl[j] = sBl[j];
        }
    }

    const int wm = wid & 3, wn = wid >> 2;
    const int wrow = wm * 32, wcol = wn * 32;
    const int lr = lane & 15, lc = lane >> 4;

    int t = blockIdx.x;
    prefetchA(t, sb + OFF_A0, Nn);
    CP_COMMIT();
    int buf = 0;

    for (; t < ntiles; t += gridDim.x) {
        int tn = t + gridDim.x;
        if (tn < ntiles) prefetchA(tn, sb + (buf ? OFF_A0 : OFF_A1), Nn);
        CP_COMMIT();
        CP_WAIT1();              // A(t) landed (and B on first iter)
        __syncthreads();
        if (tid < 128) { s_ua[tid] = 0.f; s_ud[tid] = 0.f; }

        const uint32_t abase = sb + (buf ? OFF_A1 : OFF_A0);
        float acc[2][4][4];
#pragma unroll
        for (int i = 0; i < 2; i++)
#pragma unroll
            for (int j = 0; j < 4; j++)
#pragma unroll
                for (int q = 0; q < 4; q++) acc[i][j][q] = 0.f;

#pragma unroll
        for (int pass = 0; pass < 3; pass++) {
            uint32_t aoff = abase + ((pass == 1) ? TILE_B : 0);
            uint32_t boff = sb + ((pass == 2) ? OFF_BL : OFF_BH);
#pragma unroll
            for (int ks = 0; ks < 8; ks++) {
                int k0 = ks * 16;
                uint32_t a[2][4], b[2][4];
#pragma unroll
                for (int mt = 0; mt < 2; mt++)
                    ldsm_x4(a[mt], aoff + ((wrow + mt * 16 + lr) * AS_STRIDE + lc * 8 + k0) * 2);
#pragma unroll
                for (int ng = 0; ng < 2; ng++)
                    ldsm_x4_t(b[ng], boff + ((k0 + lr) * AS_STRIDE + wcol + ng * 16 + lc * 8) * 2);
#pragma unroll
                for (int mt = 0; mt < 2; mt++)
#pragma unroll
                    for (int nt = 0; nt < 4; nt++)
                        mma_bf16(acc[mt][nt], a[mt], &b[nt >> 1][(nt & 1) * 2]);
            }
        }

        const int row0 = t * 128;
        float pa[4] = {0.f, 0.f, 0.f, 0.f}, pd[4] = {0.f, 0.f, 0.f, 0.f};
#pragma unroll
        for (int mt = 0; mt < 2; mt++) {
#pragma unroll
            for (int half = 0; half < 2; half++) {
                int rl = wrow + mt * 16 + half * 8 + (lane >> 2);
                int gr = row0 + rl;
                bool ok = gr < Nn;
#pragma unroll
                for (int nt = 0; nt < 4; nt++) {
                    int cl = wcol + nt * 8 + (lane & 3) * 2;
                    float v0 = acc[mt][nt][half * 2 + 0];
                    float v1 = acc[mt][nt][half * 2 + 1];
                    if (ok) *(__half2*)&g_h[(size_t)gr * 128 + cl] = __floats2half2_rn(v0, v1);
                    pa[mt * 2 + half] += v0 * s_as[cl] + v1 * s_as[cl + 1];
                    pd[mt * 2 + half] += v0 * s_ad[cl] + v1 * s_ad[cl + 1];
                }
            }
        }
        __syncthreads();   // s_ua/s_ud zero visible; all compute reads of A(buf) done
#pragma unroll
        for (int i = 0; i < 4; i++) {
            int rl = wrow + (i >> 1) * 16 + (i & 1) * 8 + (lane >> 2);
            atomicAdd(&s_ua[rl], pa[i]);
            atomicAdd(&s_ud[rl], pd[i]);
        }
        __syncthreads();
        if (tid < 128 && row0 + tid < Nn) {
            g_asrc[row0 + tid] = s_ua[tid];
            g_adst[row0 + tid] = s_ud[tid];
        }
        buf ^= 1;
    }
}

// ---------------- softmax aggregation: one warp per dst; deg<=32 fast path ----------
__global__ void k_aggregate(const float* __restrict__ bias, float* __restrict__ outp,
                            int N, int write_final) {
    int warp = (blockIdx.x * blockDim.x + threadIdx.x) >> 5;
    int lane = threadIdx.x & 31;
    if (warp >= N) return;

    int beg = g_rowptr[warp];
    int end = g_rowptr[warp + 1];
    float ad = g_adst[warp];

    float4 acc = make_float4(0.f, 0.f, 0.f, 0.f);
    float denom = 0.f;

    if (end - beg <= 32) {
        int e = beg + lane;
        int s = 0;
        float v = -1e30f;
        if (e < end) {
            s = __ldg(&g_srcs[e]);
            float t = __ldg(&g_asrc[s]) + ad;
            v = t > 0.f ? t : 0.2f * t;
        }
        float m = v;
#pragma unroll
        for (int off = 16; off; off >>= 1)
            m = fmaxf(m, __shfl_xor_sync(0xffffffffu, m, off));
        float w = __expf(v - m);
        denom = w;
        int cnt = end - beg;
        for (int i = 0; i < cnt; i++) {
            float wi = __shfl_sync(0xffffffffu, w, i);
            int   si = __shfl_sync(0xffffffffu, s, i);
            uint2 raw = __ldg((const uint2*)&g_h[(size_t)si * 128 + lane * 4]);
            __half2 h01 = *reinterpret_cast<__half2*>(&raw.x);
            __half2 h23 = *reinterpret_cast<__half2*>(&raw.y);
            float2 f01 = __half22float2(h01);
            float2 f23 = __half22float2(h23);
            acc.x += wi * f01.x; acc.y += wi * f01.y;
            acc.z += wi * f23.x; acc.w += wi * f23.y;
        }
    } else {
        float m = -1e30f;
        for (int e = beg + lane; e < end; e += 32) {
            int s = __ldg(&g_srcs[e]);
            float v = __ldg(&g_asrc[s]) + ad;
            v = v > 0.f ? v : 0.2f * v;
            m = fmaxf(m, v);
        }
#pragma unroll
        for (int off = 16; off; off >>= 1)
            m = fmaxf(m, __shfl_xor_sync(0xffffffffu, m, off));
        for (int base = beg; base < end; base += 32) {
            int e = base + lane;
            float w = 0.f;
            int s = 0;
            if (e < end) {
                s = __ldg(&g_srcs[e]);
                float v = __ldg(&g_asrc[s]) + ad;
                v = v > 0.f ? v : 0.2f * v;
                w = __expf(v - m);
            }
            denom += w;
            int cnt = min(32, end - base);
            for (int i = 0; i < cnt; i++) {
                float wi = __shfl_sync(0xffffffffu, w, i);
                int   si = __shfl_sync(0xffffffffu, s, i);
                uint2 raw = __ldg((const uint2*)&g_h[(size_t)si * 128 + lane * 4]);
                __half2 h01 = *reinterpret_cast<__half2*>(&raw.x);
                __half2 h23 = *reinterpret_cast<__half2*>(&raw.y);
                float2 f01 = __half22float2(h01);
                float2 f23 = __half22float2(h23);
                acc.x += wi * f01.x; acc.y += wi * f01.y;
                acc.z += wi * f23.x; acc.w += wi * f23.y;
            }
        }
    }
#pragma unroll
    for (int off = 16; off; off >>= 1)
        denom += __shfl_xor_sync(0xffffffffu, denom, off);

    float inv = 1.f / denom;
    float4 bv = *(const float4*)&bias[lane * 4];
    float4 r;
    r.x = acc.x * inv + bv.x;
    r.y = acc.y * inv + bv.y;
    r.z = acc.z * inv + bv.z;
    r.w = acc.w * inv + bv.w;
    if (write_final) {
        *(float4*)&outp[(size_t)warp * 128 + lane * 4] = r;
    } else {
        r.x = r.x > 0.f ? r.x : expm1f(r.x);
        r.y = r.y > 0.f ? r.y : expm1f(r.y);
        r.z = r.z > 0.f ? r.z : expm1f(r.z);
        r.w = r.w > 0.f ? r.w : expm1f(r.w);
        size_t idx = (size_t)warp * 128 + lane * 4;
        split4_store(r, &g_xh[idx], &g_xl[idx]);
    }
}

// ---------------- launch: CSR build overlapped on a side stream ----------------
extern "C" void kernel_launch(void* const* d_in, const int* in_sizes, int n_in,
                              void* d_out, int out_size) {
    const float* x  = (const float*)d_in[0];
    const int*   ei = (const int*)d_in[1];
    int N  = in_sizes[0] / F;
    int E  = in_sizes[1] / 2;
    int ET = E + N;
    int nb = (N + 1023) / 1024;
    int ntiles = (N + 127) / 128;

    static cudaStream_t s1;
    static cudaEvent_t e0, e1;
    static int inited = 0;
    if (!inited) {
        cudaFuncSetAttribute(k_gemm_mma, cudaFuncAttributeMaxDynamicSharedMemorySize, GEMM_SMEM);
        cudaStreamCreateWithFlags(&s1, cudaStreamNonBlocking);
        cudaEventCreateWithFlags(&e0, cudaEventDisableTiming);
        cudaEventCreateWithFlags(&e1, cudaEventDisableTiming);
        inited = 1;
    }

    int warp_blocks = (N * 32 + 255) / 256;

    // fork: CSR chain on side stream (independent of GEMM prologue)
    cudaEventRecord(e0, 0);
    cudaStreamWaitEvent(s1, e0, 0);
    k_zero_deg<<<(N + 255) / 256, 256, 0, s1>>>(N);
    k_count<<<(ET + 255) / 256, 256, 0, s1>>>(ei, E, N);
    k_scan1<<<nb, 256, 0, s1>>>(N);
    k_scan2<<<1, 256, 0, s1>>>(nb);
    k_scan3<<<nb, 256, 0, s1>>>(N, nb);
    k_scatter<<<(ET + 255) / 256, 256, 0, s1>>>(ei, E, N);
    cudaEventRecord(e1, s1);

    // main stream: layer-0 compute prologue
    k_split_x<<<(N * 32 + 255) / 256, 256>>>(x, N * 32);
    k_prepW_all<<<48, 256>>>((const float*)d_in[2], (const float*)d_in[6], (const float*)d_in[10]);
    k_gemm_mma<<<148, 512, GEMM_SMEM>>>(0, (const float*)d_in[3], (const float*)d_in[4], N, ntiles);

    // join: aggregate needs CSR + GEMM0
    cudaStreamWaitEvent(0, e1, 0);

    for (int l = 0; l < 3; l++) {
        const float* as = (const float*)d_in[3 + 4 * l];
        const float* ad = (const float*)d_in[4 + 4 * l];
        const float* b  = (const float*)d_in[5 + 4 * l];
        if (l > 0)
            k_gemm_mma<<<148, 512, GEMM_SMEM>>>(l, as, ad, N, ntiles);
        k_aggregate<<<warp_blocks, 256>>>(b, l == 2 ? (float*)d_out : nullptr, N, l == 2 ? 1 : 0);
    }
}

// round 15
// speedup vs baseline: 1.1782x; 1.0134x over previous
#include <cuda_runtime.h>
#include <cuda_bf16.h>
#include <cuda_fp16.h>
#include <stdint.h>

#define F 128
#define NMAX 100000
#define EMAX 1700000   // E + N self loops

// ---------------- scratch (alloc-free: __device__ globals) ----------------
__device__ __half g_h[NMAX * F];                // transformed features h = feat @ W (fp16)
__device__ __nv_bfloat16 g_xh[NMAX * F];        // layer-1/2 input, bf16 hi (from aggregate)
__device__ __nv_bfloat16 g_xl[NMAX * F];        // layer-1/2 input, bf16 lo
__device__ __nv_bfloat16 g_wh[3][F * F];        // W bf16 hi per layer
__device__ __nv_bfloat16 g_wl[3][F * F];        // W bf16 lo per layer
__device__ float g_asrc[NMAX];
__device__ float g_adst[NMAX];
__device__ int   g_deg[NMAX];
__device__ int   g_rowptr[NMAX + 1];
__device__ int   g_cursor[NMAX];
__device__ int   g_srcs[EMAX];                  // src indices sorted by dst (CSR)
__device__ int   g_bsum[256];                   // scan block sums

// ---------------- helpers ----------------
__device__ __forceinline__ uint32_t smem_u32(const void* p) {
    uint32_t a;
    asm("{ .reg .u64 t; cvta.to.shared.u64 t, %1; cvt.u32.u64 %0, t; }" : "=r"(a) : "l"(p));
    return a;
}
__device__ __forceinline__ void ldsm_x4(uint32_t* r, uint32_t addr) {
    asm volatile("ldmatrix.sync.aligned.m8n8.x4.shared.b16 {%0,%1,%2,%3}, [%4];"
                 : "=r"(r[0]), "=r"(r[1]), "=r"(r[2]), "=r"(r[3]) : "r"(addr));
}
__device__ __forceinline__ void ldsm_x4_t(uint32_t* r, uint32_t addr) {
    asm volatile("ldmatrix.sync.aligned.m8n8.x4.trans.shared.b16 {%0,%1,%2,%3}, [%4];"
                 : "=r"(r[0]), "=r"(r[1]), "=r"(r[2]), "=r"(r[3]) : "r"(addr));
}
__device__ __forceinline__ void mma_bf16(float* c, const uint32_t* a, const uint32_t* b) {
    asm volatile("mma.sync.aligned.m16n8k16.row.col.f32.bf16.bf16.f32 "
                 "{%0,%1,%2,%3}, {%4,%5,%6,%7}, {%8,%9}, {%0,%1,%2,%3};"
                 : "+f"(c[0]), "+f"(c[1]), "+f"(c[2]), "+f"(c[3])
                 : "r"(a[0]), "r"(a[1]), "r"(a[2]), "r"(a[3]), "r"(b[0]), "r"(b[1]));
}
#define CP_ASYNC16(dst, src) \
    asm volatile("cp.async.cg.shared.global [%0], [%1], 16;" :: "r"(dst), "l"(src) : "memory")
#define CP_COMMIT()   asm volatile("cp.async.commit_group;" ::: "memory")
#define CP_WAIT1()    asm volatile("cp.async.wait_group 1;" ::: "memory")

__device__ __forceinline__ void split_bf16(float x, __nv_bfloat16& h, __nv_bfloat16& l) {
    h = __float2bfloat16_rn(x);
    l = __float2bfloat16_rn(x - __bfloat162float(h));
}
__device__ __forceinline__ void split4_store(float4 r, __nv_bfloat16* ph, __nv_bfloat16* pl) {
    __nv_bfloat16 h0, l0, h1, l1, h2, l2, h3, l3;
    split_bf16(r.x, h0, l0); split_bf16(r.y, h1, l1);
    split_bf16(r.z, h2, l2); split_bf16(r.w, h3, l3);
    uint2 hp, lp;
    hp.x = (uint32_t)__bfloat16_as_ushort(h0) | ((uint32_t)__bfloat16_as_ushort(h1) << 16);
    hp.y = (uint32_t)__bfloat16_as_ushort(h2) | ((uint32_t)__bfloat16_as_ushort(h3) << 16);
    lp.x = (uint32_t)__bfloat16_as_ushort(l0) | ((uint32_t)__bfloat16_as_ushort(l1) << 16);
    lp.y = (uint32_t)__bfloat16_as_ushort(l2) | ((uint32_t)__bfloat16_as_ushort(l3) << 16);
    *(uint2*)ph = hp;
    *(uint2*)pl = lp;
}

// ---------------- weight splitting ----------------
__global__ void k_prepW_all(const float* __restrict__ W0, const float* __restrict__ W1,
                            const float* __restrict__ W2) {
    int i = blockIdx.x * blockDim.x + threadIdx.x;
    if (i >= 3 * 4096) return;
    int l = i >> 12, j = i & 4095;
    const float* W = (l == 0) ? W0 : (l == 1) ? W1 : W2;
    float4 v = ((const float4*)W)[j];
    split4_store(v, &g_wh[l][j * 4], &g_wl[l][j * 4]);
}

// ---------------- CSR build ----------------
__global__ void k_zero_deg(int N) {
    int i = blockIdx.x * blockDim.x + threadIdx.x;
    if (i < N) g_deg[i] = 0;
}
__global__ void k_count(const int* __restrict__ ei, int E, int N) {
    int j = blockIdx.x * blockDim.x + threadIdx.x;
    if (j >= E + N) return;
    int d = (j < E) ? ei[E + j] : (j - E);
    atomicAdd(&g_deg[d], 1);
}
__global__ void k_scan1(int N) {
    __shared__ int s[256];
    int t = threadIdx.x, b = blockIdx.x;
    int i0 = b * 1024 + t * 4;
    int sum = 0;
#pragma unroll
    for (int j = 0; j < 4; j++)
        if (i0 + j < N) sum += g_deg[i0 + j];
    s[t] = sum;
    __syncthreads();
#pragma unroll
    for (int off = 128; off; off >>= 1) {
        if (t < off) s[t] += s[t + off];
        __syncthreads();
    }
    if (t == 0) g_bsum[b] = s[0];
}
// scan3 also performs the top-level scan of block sums itself (scan2 eliminated)
__global__ void k_scan3(int N, int nb) {
    __shared__ int s[256];
    __shared__ int s2[256];
    int t = threadIdx.x, b = blockIdx.x;
    int i0 = b * 1024 + t * 4;
    int d[4];
    int sum = 0;
#pragma unroll
    for (int j = 0; j < 4; j++) {
        d[j] = (i0 + j < N) ? g_deg[i0 + j] : 0;
        sum += d[j];
    }
    s[t] = sum;
    s2[t] = (t < nb) ? g_bsum[t] : 0;
    __syncthreads();
#pragma unroll
    for (int off = 1; off < 256; off <<= 1) {
        int u  = (t >= off) ? s[t - off]  : 0;
        int u2 = (t >= off) ? s2[t - off] : 0;
        __syncthreads();
        s[t] += u;
        s2[t] += u2;
        __syncthreads();
    }
    int bpre = (b == 0) ? 0 : s2[b - 1];
    int run = bpre + s[t] - sum;
#pragma unroll
    for (int j = 0; j < 4; j++) {
        if (i0 + j < N) {
            g_rowptr[i0 + j] = run;
            g_cursor[i0 + j] = run;
        }
        run += d[j];
    }
    if (b == 0 && t == 0) g_rowptr[N] = s2[nb - 1];
}
__global__ void k_scatter(const int* __restrict__ ei, int E, int N) {
    int j = blockIdx.x * blockDim.x + threadIdx.x;
    if (j >= E + N) return;
    int sIdx, d;
    if (j < E) { sIdx = ei[j]; d = ei[E + j]; }
    else       { sIdx = j - E; d = j - E; }
    int pos = atomicAdd(&g_cursor[d], 1);
    g_srcs[pos] = sIdx;
}

// ---------------- persistent bf16x3 tensor-core GEMM ----------------
// grid=148, 512 threads, 16 warps 4(M)x4(N), warp tile 32x32. B staged once/CTA.
// layer 0: A staged straight from fp32 x with inline bf16 hi/lo split (no split_x kernel).
// layers 1-2: cp.async double-buffered A from pre-split g_xh/g_xl.
#define AS_STRIDE 136
#define TILE_B (128 * AS_STRIDE * 2)     // 34816 bytes per 128x128 bf16 image
#define OFF_BH 0
#define OFF_BL (TILE_B)
#define OFF_A0 (2 * TILE_B)              // buf0: Ah at +0, Al at +TILE_B
#define OFF_A1 (4 * TILE_B)              // buf1
#define OFF_SAS (6 * TILE_B)
#define OFF_SAD (OFF_SAS + 512)
#define OFF_SUA (OFF_SAD + 512)
#define OFF_SUD (OFF_SUA + 512)
#define GEMM_SMEM (OFF_SUD + 512)        // 210944 bytes

__device__ __forceinline__ void prefetchA(int t, uint32_t abuf, int Nn) {
    int tid = threadIdx.x;
    int r = tid >> 2, seg = (tid & 3) * 32;
    int gr = min(t * 128 + r, Nn - 1);
    const char* sh = (const char*)&g_xh[(size_t)gr * 128 + seg];
    const char* sl = (const char*)&g_xl[(size_t)gr * 128 + seg];
    uint32_t dh = abuf + (uint32_t)(r * AS_STRIDE + seg) * 2;
    uint32_t dl = dh + TILE_B;
#pragma unroll
    for (int j = 0; j < 4; j++) {
        CP_ASYNC16(dh + j * 16, sh + j * 16);
        CP_ASYNC16(dl + j * 16, sl + j * 16);
    }
}

// layer 0: synchronous stage of A tile from fp32 x with inline split (buf0 only)
__device__ __forceinline__ void stageA0(const float* __restrict__ x0, int t,
                                        char* smem, int Nn) {
    int tid = threadIdx.x;
    int r = tid >> 2, seg = (tid & 3) * 32;
    int gr = min(t * 128 + r, Nn - 1);
    const float4* src = (const float4*)&x0[(size_t)gr * 128 + seg];
    __nv_bfloat16* dh = (__nv_bfloat16*)(smem + OFF_A0) + r * AS_STRIDE + seg;
    __nv_bfloat16* dl = dh + (TILE_B / 2);   // Al image is TILE_B bytes after Ah
#pragma unroll
    for (int j = 0; j < 8; j++)
        split4_store(src[j], dh + j * 4, dl + j * 4);
}

__global__ void __launch_bounds__(512)
k_gemm_mma(int layer, const float* __restrict__ x0,
           const float* __restrict__ av_s, const float* __restrict__ av_d,
           int Nn, int ntiles) {
    extern __shared__ char smem[];
    const uint32_t sb = smem_u32(smem);
    const int tid = threadIdx.x, lane = tid & 31, wid = tid >> 5;

    float* s_as = (float*)(smem + OFF_SAS);
    float* s_ad = (float*)(smem + OFF_SAD);
    float* s_ua = (float*)(smem + OFF_SUA);
    float* s_ud = (float*)(smem + OFF_SUD);
    if (tid < 128) {
        s_as[tid] = av_s[tid];
        s_ad[tid] = av_d[tid];
    }

    {   // stage B once: 128 rows, 4 threads/row, 32 bf16 (4 uint4) per image
        int r = tid >> 2, seg = (tid & 3) * 32;
        const uint4* sBh = (const uint4*)&g_wh[layer][r * 128 + seg];
        const uint4* sBl = (const uint4*)&g_wl[layer][r * 128 + seg];
        uint4* dBh = (uint4*)((__nv_bfloat16*)(smem + OFF_BH) + r * AS_STRIDE + seg);
        uint4* dBl = (uint4*)((__nv_bfloat16*)(smem + OFF_BL) + r * AS_STRIDE + seg);
#pragma unroll
        for (int j = 0; j < 4; j++) {
            dBh[j] = sBh[j];
            dBl[j] = sBl[j];
        }
    }

    const int wm = wid & 3, wn = wid >> 2;
    const int wrow = wm * 32, wcol = wn * 32;
    const int lr = lane & 15, lc = lane >> 4;

    int t = blockIdx.x;
    if (layer != 0) {
        prefetchA(t, sb + OFF_A0, Nn);
        CP_COMMIT();
    }
    int buf = 0;

    for (; t < ntiles; t += gridDim.x) {
        if (layer == 0) {
            stageA0(x0, t, smem, Nn);
        } else {
            int tn = t + gridDim.x;
            if (tn < ntiles) prefetchA(tn, sb + (buf ? OFF_A0 : OFF_A1), Nn);
            CP_COMMIT();
            CP_WAIT1();          // A(t) landed
        }
        __syncthreads();         // staging (and B on first iter) visible
        if (tid < 128) { s_ua[tid] = 0.f; s_ud[tid] = 0.f; }

        const uint32_t abase = (layer == 0) ? (sb + OFF_A0)
                                            : (sb + (buf ? OFF_A1 : OFF_A0));
        float acc[2][4][4];
#pragma unroll
        for (int i = 0; i < 2; i++)
#pragma unroll
            for (int j = 0; j < 4; j++)
#pragma unroll
                for (int q = 0; q < 4; q++) acc[i][j][q] = 0.f;

#pragma unroll
        for (int pass = 0; pass < 3; pass++) {
            uint32_t aoff = abase + ((pass == 1) ? TILE_B : 0);
            uint32_t boff = sb + ((pass == 2) ? OFF_BL : OFF_BH);
#pragma unroll
            for (int ks = 0; ks < 8; ks++) {
                int k0 = ks * 16;
                uint32_t a[2][4], b[2][4];
#pragma unroll
                for (int mt = 0; mt < 2; mt++)
                    ldsm_x4(a[mt], aoff + ((wrow + mt * 16 + lr) * AS_STRIDE + lc * 8 + k0) * 2);
#pragma unroll
                for (int ng = 0; ng < 2; ng++)
                    ldsm_x4_t(b[ng], boff + ((k0 + lr) * AS_STRIDE + wcol + ng * 16 + lc * 8) * 2);
#pragma unroll
                for (int mt = 0; mt < 2; mt++)
#pragma unroll
                    for (int nt = 0; nt < 4; nt++)
                        mma_bf16(acc[mt][nt], a[mt], &b[nt >> 1][(nt & 1) * 2]);
            }
        }

        const int row0 = t * 128;
        float pa[4] = {0.f, 0.f, 0.f, 0.f}, pd[4] = {0.f, 0.f, 0.f, 0.f};
#pragma unroll
        for (int mt = 0; mt < 2; mt++) {
#pragma unroll
            for (int half = 0; half < 2; half++) {
                int rl = wrow + mt * 16 + half * 8 + (lane >> 2);
                int gr = row0 + rl;
                bool ok = gr < Nn;
#pragma unroll
                for (int nt = 0; nt < 4; nt++) {
                    int cl = wcol + nt * 8 + (lane & 3) * 2;
                    float v0 = acc[mt][nt][half * 2 + 0];
                    float v1 = acc[mt][nt][half * 2 + 1];
                    if (ok) *(__half2*)&g_h[(size_t)gr * 128 + cl] = __floats2half2_rn(v0, v1);
                    pa[mt * 2 + half] += v0 * s_as[cl] + v1 * s_as[cl + 1];
                    pd[mt * 2 + half] += v0 * s_ad[cl] + v1 * s_ad[cl + 1];
                }
            }
        }
        __syncthreads();   // all compute reads of A buffer done; s_ua/s_ud zero visible
#pragma unroll
        for (int i = 0; i < 4; i++) {
            int rl = wrow + (i >> 1) * 16 + (i & 1) * 8 + (lane >> 2);
            atomicAdd(&s_ua[rl], pa[i]);
            atomicAdd(&s_ud[rl], pd[i]);
        }
        __syncthreads();
        if (tid < 128 && row0 + tid < Nn) {
            g_asrc[row0 + tid] = s_ua[tid];
            g_adst[row0 + tid] = s_ud[tid];
        }
        buf ^= 1;
    }
}

// ---------------- softmax aggregation: one warp per dst; deg<=32 fast path ----------
__global__ void k_aggregate(const float* __restrict__ bias, float* __restrict__ outp,
                            int N, int write_final) {
    int warp = (blockIdx.x * blockDim.x + threadIdx.x) >> 5;
    int lane = threadIdx.x & 31;
    if (warp >= N) return;

    int beg = g_rowptr[warp];
    int end = g_rowptr[warp + 1];
    float ad = g_adst[warp];

    float4 acc = make_float4(0.f, 0.f, 0.f, 0.f);
    float denom = 0.f;

    if (end - beg <= 32) {
        int e = beg + lane;
        int s = 0;
        float v = -1e30f;
        if (e < end) {
            s = __ldg(&g_srcs[e]);
            float t = __ldg(&g_asrc[s]) + ad;
            v = t > 0.f ? t : 0.2f * t;
        }
        float m = v;
#pragma unroll
        for (int off = 16; off; off >>= 1)
            m = fmaxf(m, __shfl_xor_sync(0xffffffffu, m, off));
        float w = __expf(v - m);
        denom = w;
        int cnt = end - beg;
        for (int i = 0; i < cnt; i++) {
            float wi = __shfl_sync(0xffffffffu, w, i);
            int   si = __shfl_sync(0xffffffffu, s, i);
            uint2 raw = __ldg((const uint2*)&g_h[(size_t)si * 128 + lane * 4]);
            __half2 h01 = *reinterpret_cast<__half2*>(&raw.x);
            __half2 h23 = *reinterpret_cast<__half2*>(&raw.y);
            float2 f01 = __half22float2(h01);
            float2 f23 = __half22float2(h23);
            acc.x += wi * f01.x; acc.y += wi * f01.y;
            acc.z += wi * f23.x; acc.w += wi * f23.y;
        }
    } else {
        float m = -1e30f;
        for (int e = beg + lane; e < end; e += 32) {
            int s = __ldg(&g_srcs[e]);
            float v = __ldg(&g_asrc[s]) + ad;
            v = v > 0.f ? v : 0.2f * v;
            m = fmaxf(m, v);
        }
#pragma unroll
        for (int off = 16; off; off >>= 1)
            m = fmaxf(m, __shfl_xor_sync(0xffffffffu, m, off));
        for (int base = beg; base < end; base += 32) {
            int e = base + lane;
            float w = 0.f;
            int s = 0;
            if (e < end) {
                s = __ldg(&g_srcs[e]);
                float v = __ldg(&g_asrc[s]) + ad;
                v = v > 0.f ? v : 0.2f * v;
                w = __expf(v - m);
            }
            denom += w;
            int cnt = min(32, end - base);
            for (int i = 0; i < cnt; i++) {
                float wi = __shfl_sync(0xffffffffu, w, i);
                int   si = __shfl_sync(0xffffffffu, s, i);
                uint2 raw = __ldg((const uint2*)&g_h[(size_t)si * 128 + lane * 4]);
                __half2 h01 = *reinterpret_cast<__half2*>(&raw.x);
                __half2 h23 = *reinterpret_cast<__half2*>(&raw.y);
                float2 f01 = __half22float2(h01);
                float2 f23 = __half22float2(h23);
                acc.x += wi * f01.x; acc.y += wi * f01.y;
                acc.z += wi * f23.x; acc.w += wi * f23.y;
            }
        }
    }
#pragma unroll
    for (int off = 16; off; off >>= 1)
        denom += __shfl_xor_sync(0xffffffffu, denom, off);

    float inv = 1.f / denom;
    float4 bv = *(const float4*)&bias[lane * 4];
    float4 r;
    r.x = acc.x * inv + bv.x;
    r.y = acc.y * inv + bv.y;
    r.z = acc.z * inv + bv.z;
    r.w = acc.w * inv + bv.w;
    if (write_final) {
        *(float4*)&outp[(size_t)warp * 128 + lane * 4] = r;
    } else {
        r.x = r.x > 0.f ? r.x : expm1f(r.x);
        r.y = r.y > 0.f ? r.y : expm1f(r.y);
        r.z = r.z > 0.f ? r.z : expm1f(r.z);
        r.w = r.w > 0.f ? r.w : expm1f(r.w);
        size_t idx = (size_t)warp * 128 + lane * 4;
        split4_store(r, &g_xh[idx], &g_xl[idx]);
    }
}

// ---------------- launch: CSR build overlapped on a side stream ----------------
extern "C" void kernel_launch(void* const* d_in, const int* in_sizes, int n_in,
                              void* d_out, int out_size) {
    const float* x  = (const float*)d_in[0];
    const int*   ei = (const int*)d_in[1];
    int N  = in_sizes[0] / F;
    int E  = in_sizes[1] / 2;
    int ET = E + N;
    int nb = (N + 1023) / 1024;
    int ntiles = (N + 127) / 128;

    static cudaStream_t s1;
    static cudaEvent_t e0, e1;
    static int inited = 0;
    if (!inited) {
        cudaFuncSetAttribute(k_gemm_mma, cudaFuncAttributeMaxDynamicSharedMemorySize, GEMM_SMEM);
        cudaStreamCreateWithFlags(&s1, cudaStreamNonBlocking);
        cudaEventCreateWithFlags(&e0, cudaEventDisableTiming);
        cudaEventCreateWithFlags(&e1, cudaEventDisableTiming);
        inited = 1;
    }

    int warp_blocks = (N * 32 + 255) / 256;

    // fork: CSR chain on side stream (independent of GEMM prologue)
    cudaEventRecord(e0, 0);
    cudaStreamWaitEvent(s1, e0, 0);
    k_zero_deg<<<(N + 255) / 256, 256, 0, s1>>>(N);
    k_count<<<(ET + 255) / 256, 256, 0, s1>>>(ei, E, N);
    k_scan1<<<nb, 256, 0, s1>>>(N);
    k_scan3<<<nb, 256, 0, s1>>>(N, nb);
    k_scatter<<<(ET + 255) / 256, 256, 0, s1>>>(ei, E, N);
    cudaEventRecord(e1, s1);

    // main stream: layer-0 compute prologue (split_x folded into GEMM0 staging)
    k_prepW_all<<<48, 256>>>((const float*)d_in[2], (const float*)d_in[6], (const float*)d_in[10]);
    k_gemm_mma<<<148, 512, GEMM_SMEM>>>(0, x, (const float*)d_in[3], (const float*)d_in[4], N, ntiles);

    // join: aggregate needs CSR + GEMM0
    cudaStreamWaitEvent(0, e1, 0);

    for (int l = 0; l < 3; l++) {
        const float* as = (const float*)d_in[3 + 4 * l];
        const float* ad = (const float*)d_in[4 + 4 * l];
        const float* b  = (const float*)d_in[5 + 4 * l];
        if (l > 0)
            k_gemm_mma<<<148, 512, GEMM_SMEM>>>(l, nullptr, as, ad, N, ntiles);
        k_aggregate<<<warp_blocks, 256>>>(b, l == 2 ? (float*)d_out : nullptr, N, l == 2 ? 1 : 0);
    }
}

// round 16
// speedup vs baseline: 1.2620x; 1.0711x over previous
#include <cuda_runtime.h>
#include <cuda_bf16.h>
#include <cuda_fp16.h>
#include <stdint.h>

#define F 128
#define NMAX 100000
#define EMAX 1700000   // E + N self loops

// ---------------- scratch (alloc-free: __device__ globals) ----------------
__device__ __half g_h[NMAX * F];                // transformed features h = feat @ W (fp16)
__device__ __nv_bfloat16 g_xh[NMAX * F];        // layer-1/2 input, bf16 hi (from aggregate)
__device__ __nv_bfloat16 g_xl[NMAX * F];        // layer-1/2 input, bf16 lo
__device__ __nv_bfloat16 g_wh[3][F * F];        // W bf16 hi per layer (layers 1-2 use)
__device__ __nv_bfloat16 g_wl[3][F * F];        // W bf16 lo per layer
__device__ float g_asrc[NMAX];
__device__ float g_adst[NMAX];
__device__ int   g_deg[NMAX];
__device__ int   g_rowptr[NMAX + 1];
__device__ int   g_cursor[NMAX];
__device__ int   g_srcs[EMAX];                  // src indices sorted by dst (CSR)
__device__ int   g_bsum[256];                   // scan block sums

// ---------------- helpers ----------------
__device__ __forceinline__ uint32_t smem_u32(const void* p) {
    uint32_t a;
    asm("{ .reg .u64 t; cvta.to.shared.u64 t, %1; cvt.u32.u64 %0, t; }" : "=r"(a) : "l"(p));
    return a;
}
__device__ __forceinline__ void ldsm_x4(uint32_t* r, uint32_t addr) {
    asm volatile("ldmatrix.sync.aligned.m8n8.x4.shared.b16 {%0,%1,%2,%3}, [%4];"
                 : "=r"(r[0]), "=r"(r[1]), "=r"(r[2]), "=r"(r[3]) : "r"(addr));
}
__device__ __forceinline__ void ldsm_x4_t(uint32_t* r, uint32_t addr) {
    asm volatile("ldmatrix.sync.aligned.m8n8.x4.trans.shared.b16 {%0,%1,%2,%3}, [%4];"
                 : "=r"(r[0]), "=r"(r[1]), "=r"(r[2]), "=r"(r[3]) : "r"(addr));
}
__device__ __forceinline__ void mma_bf16(float* c, const uint32_t* a, const uint32_t* b) {
    asm volatile("mma.sync.aligned.m16n8k16.row.col.f32.bf16.bf16.f32 "
                 "{%0,%1,%2,%3}, {%4,%5,%6,%7}, {%8,%9}, {%0,%1,%2,%3};"
                 : "+f"(c[0]), "+f"(c[1]), "+f"(c[2]), "+f"(c[3])
                 : "r"(a[0]), "r"(a[1]), "r"(a[2]), "r"(a[3]), "r"(b[0]), "r"(b[1]));
}
#define CP_ASYNC16(dst, src) \
    asm volatile("cp.async.cg.shared.global [%0], [%1], 16;" :: "r"(dst), "l"(src) : "memory")
#define CP_COMMIT()   asm volatile("cp.async.commit_group;" ::: "memory")
#define CP_WAIT1()    asm volatile("cp.async.wait_group 1;" ::: "memory")

__device__ __forceinline__ void split_bf16(float x, __nv_bfloat16& h, __nv_bfloat16& l) {
    h = __float2bfloat16_rn(x);
    l = __float2bfloat16_rn(x - __bfloat162float(h));
}
__device__ __forceinline__ void split4_store(float4 r, __nv_bfloat16* ph, __nv_bfloat16* pl) {
    __nv_bfloat16 h0, l0, h1, l1, h2, l2, h3, l3;
    split_bf16(r.x, h0, l0); split_bf16(r.y, h1, l1);
    split_bf16(r.z, h2, l2); split_bf16(r.w, h3, l3);
    uint2 hp, lp;
    hp.x = (uint32_t)__bfloat16_as_ushort(h0) | ((uint32_t)__bfloat16_as_ushort(h1) << 16);
    hp.y = (uint32_t)__bfloat16_as_ushort(h2) | ((uint32_t)__bfloat16_as_ushort(h3) << 16);
    lp.x = (uint32_t)__bfloat16_as_ushort(l0) | ((uint32_t)__bfloat16_as_ushort(l1) << 16);
    lp.y = (uint32_t)__bfloat16_as_ushort(l2) | ((uint32_t)__bfloat16_as_ushort(l3) << 16);
    *(uint2*)ph = hp;
    *(uint2*)pl = lp;
}

// ---------------- weight splitting (layers 1-2; runs on side stream) ----------------
__global__ void k_prepW_all(const float* __restrict__ W0, const float* __restrict__ W1,
                            const float* __restrict__ W2) {
    int i = blockIdx.x * blockDim.x + threadIdx.x;
    if (i >= 3 * 4096) return;
    int l = i >> 12, j = i & 4095;
    const float* W = (l == 0) ? W0 : (l == 1) ? W1 : W2;
    float4 v = ((const float4*)W)[j];
    split4_store(v, &g_wh[l][j * 4], &g_wl[l][j * 4]);
}

// ---------------- CSR build ----------------
__global__ void k_zero_deg(int N) {
    int i = blockIdx.x * blockDim.x + threadIdx.x;
    if (i < N) g_deg[i] = 0;
}
__global__ void k_count(const int* __restrict__ ei, int E, int N) {
    int j = blockIdx.x * blockDim.x + threadIdx.x;
    if (j >= E + N) return;
    int d = (j < E) ? ei[E + j] : (j - E);
    atomicAdd(&g_deg[d], 1);
}
__global__ void k_scan1(int N) {
    __shared__ int s[256];
    int t = threadIdx.x, b = blockIdx.x;
    int i0 = b * 1024 + t * 4;
    int sum = 0;
#pragma unroll
    for (int j = 0; j < 4; j++)
        if (i0 + j < N) sum += g_deg[i0 + j];
    s[t] = sum;
    __syncthreads();
#pragma unroll
    for (int off = 128; off; off >>= 1) {
        if (t < off) s[t] += s[t + off];
        __syncthreads();
    }
    if (t == 0) g_bsum[b] = s[0];
}
// scan3 also performs the top-level scan of block sums itself
__global__ void k_scan3(int N, int nb) {
    __shared__ int s[256];
    __shared__ int s2[256];
    int t = threadIdx.x, b = blockIdx.x;
    int i0 = b * 1024 + t * 4;
    int d[4];
    int sum = 0;
#pragma unroll
    for (int j = 0; j < 4; j++) {
        d[j] = (i0 + j < N) ? g_deg[i0 + j] : 0;
        sum += d[j];
    }
    s[t] = sum;
    s2[t] = (t < nb) ? g_bsum[t] : 0;
    __syncthreads();
#pragma unroll
    for (int off = 1; off < 256; off <<= 1) {
        int u  = (t >= off) ? s[t - off]  : 0;
        int u2 = (t >= off) ? s2[t - off] : 0;
        __syncthreads();
        s[t] += u;
        s2[t] += u2;
        __syncthreads();
    }
    int bpre = (b == 0) ? 0 : s2[b - 1];
    int run = bpre + s[t] - sum;
#pragma unroll
    for (int j = 0; j < 4; j++) {
        if (i0 + j < N) {
            g_rowptr[i0 + j] = run;
            g_cursor[i0 + j] = run;
        }
        run += d[j];
    }
    if (b == 0 && t == 0) g_rowptr[N] = s2[nb - 1];
}
__global__ void k_scatter(const int* __restrict__ ei, int E, int N) {
    int j = blockIdx.x * blockDim.x + threadIdx.x;
    if (j >= E + N) return;
    int sIdx, d;
    if (j < E) { sIdx = ei[j]; d = ei[E + j]; }
    else       { sIdx = j - E; d = j - E; }
    int pos = atomicAdd(&g_cursor[d], 1);
    g_srcs[pos] = sIdx;
}

// ---------------- persistent bf16x3 tensor-core GEMM, fused 3-product K loop ----------
// grid=148, 512 threads, 16 warps 4(M)x4(N), warp tile 32x32. B staged once/CTA.
// layer 0: A and B staged straight from fp32 with inline bf16 hi/lo split.
// layers 1-2: cp.async double-buffered A from pre-split g_xh/g_xl; B from g_wh/g_wl.
#define AS_STRIDE 136
#define TILE_B (128 * AS_STRIDE * 2)     // 34816 bytes per 128x128 bf16 image
#define OFF_BH 0
#define OFF_BL (TILE_B)
#define OFF_A0 (2 * TILE_B)              // buf0: Ah at +0, Al at +TILE_B
#define OFF_A1 (4 * TILE_B)              // buf1
#define OFF_SAS (6 * TILE_B)
#define OFF_SAD (OFF_SAS + 512)
#define OFF_SUA (OFF_SAD + 512)
#define OFF_SUD (OFF_SUA + 512)
#define GEMM_SMEM (OFF_SUD + 512)        // 210944 bytes

__device__ __forceinline__ void prefetchA(int t, uint32_t abuf, int Nn) {
    int tid = threadIdx.x;
    int r = tid >> 2, seg = (tid & 3) * 32;
    int gr = min(t * 128 + r, Nn - 1);
    const char* sh = (const char*)&g_xh[(size_t)gr * 128 + seg];
    const char* sl = (const char*)&g_xl[(size_t)gr * 128 + seg];
    uint32_t dh = abuf + (uint32_t)(r * AS_STRIDE + seg) * 2;
    uint32_t dl = dh + TILE_B;
#pragma unroll
    for (int j = 0; j < 4; j++) {
        CP_ASYNC16(dh + j * 16, sh + j * 16);
        CP_ASYNC16(dl + j * 16, sl + j * 16);
    }
}

// layer 0: synchronous stage of A tile from fp32 x with inline split (buf0 only)
__device__ __forceinline__ void stageA0(const float* __restrict__ x0, int t,
                                        char* smem, int Nn) {
    int tid = threadIdx.x;
    int r = tid >> 2, seg = (tid & 3) * 32;
    int gr = min(t * 128 + r, Nn - 1);
    const float4* src = (const float4*)&x0[(size_t)gr * 128 + seg];
    __nv_bfloat16* dh = (__nv_bfloat16*)(smem + OFF_A0) + r * AS_STRIDE + seg;
    __nv_bfloat16* dl = dh + (TILE_B / 2);
#pragma unroll
    for (int j = 0; j < 8; j++)
        split4_store(src[j], dh + j * 4, dl + j * 4);
}

__global__ void __launch_bounds__(512)
k_gemm_mma(int layer, const float* __restrict__ x0, const float* __restrict__ w0,
           const float* __restrict__ av_s, const float* __restrict__ av_d,
           int Nn, int ntiles) {
    extern __shared__ char smem[];
    const uint32_t sb = smem_u32(smem);
    const int tid = threadIdx.x, lane = tid & 31, wid = tid >> 5;

    float* s_as = (float*)(smem + OFF_SAS);
    float* s_ad = (float*)(smem + OFF_SAD);
    float* s_ua = (float*)(smem + OFF_SUA);
    float* s_ud = (float*)(smem + OFF_SUD);
    if (tid < 128) {
        s_as[tid] = av_s[tid];
        s_ad[tid] = av_d[tid];
    }

    {   // stage B once: layer0 inline-split from fp32 W0; else pre-split copies
        int r = tid >> 2, seg = (tid & 3) * 32;
        __nv_bfloat16* dh = (__nv_bfloat16*)(smem + OFF_BH) + r * AS_STRIDE + seg;
        __nv_bfloat16* dl = (__nv_bfloat16*)(smem + OFF_BL) + r * AS_STRIDE + seg;
        if (layer == 0) {
            const float4* src = (const float4*)&w0[r * 128 + seg];
#pragma unroll
            for (int j = 0; j < 8; j++)
                split4_store(src[j], dh + j * 4, dl + j * 4);
        } else {
            const uint4* sBh = (const uint4*)&g_wh[layer][r * 128 + seg];
            const uint4* sBl = (const uint4*)&g_wl[layer][r * 128 + seg];
#pragma unroll
            for (int j = 0; j < 4; j++) {
                ((uint4*)dh)[j] = sBh[j];
                ((uint4*)dl)[j] = sBl[j];
            }
        }
    }

    const int wm = wid & 3, wn = wid >> 2;
    const int wrow = wm * 32, wcol = wn * 32;
    const int lr = lane & 15, lc = lane >> 4;

    int t = blockIdx.x;
    if (layer != 0) {
        prefetchA(t, sb + OFF_A0, Nn);
        CP_COMMIT();
    }
    int buf = 0;

    for (; t < ntiles; t += gridDim.x) {
        if (layer == 0) {
            stageA0(x0, t, smem, Nn);
        } else {
            int tn = t + gridDim.x;
            if (tn < ntiles) prefetchA(tn, sb + (buf ? OFF_A0 : OFF_A1), Nn);
            CP_COMMIT();
            CP_WAIT1();          // A(t) landed
        }
        __syncthreads();         // staging (and B on first iter) visible
        if (tid < 128) { s_ua[tid] = 0.f; s_ud[tid] = 0.f; }

        const uint32_t abase = (layer == 0) ? (sb + OFF_A0)
                                            : (sb + (buf ? OFF_A1 : OFF_A0));
        float acc[2][4][4];
#pragma unroll
        for (int i = 0; i < 2; i++)
#pragma unroll
            for (int j = 0; j < 4; j++)
#pragma unroll
                for (int q = 0; q < 4; q++) acc[i][j][q] = 0.f;

        // fused K loop: each fragment loaded ONCE per K-step, 3 products issued
#pragma unroll
        for (int ks = 0; ks < 8; ks++) {
            int k0 = ks * 16;
            uint32_t ah[2][4], al[2][4], bh[2][4], bl[2][4];
#pragma unroll
            for (int mt = 0; mt < 2; mt++) {
                uint32_t aoff = abase + ((wrow + mt * 16 + lr) * AS_STRIDE + lc * 8 + k0) * 2;
                ldsm_x4(ah[mt], aoff);
                ldsm_x4(al[mt], aoff + TILE_B);
            }
#pragma unroll
            for (int ng = 0; ng < 2; ng++) {
                uint32_t boff = sb + ((k0 + lr) * AS_STRIDE + wcol + ng * 16 + lc * 8) * 2;
                ldsm_x4_t(bh[ng], boff + OFF_BH);
                ldsm_x4_t(bl[ng], boff + OFF_BL);
            }
#pragma unroll
            for (int mt = 0; mt < 2; mt++)
#pragma unroll
                for (int nt = 0; nt < 4; nt++) {
                    const uint32_t* pbh = &bh[nt >> 1][(nt & 1) * 2];
                    const uint32_t* pbl = &bl[nt >> 1][(nt & 1) * 2];
                    mma_bf16(acc[mt][nt], ah[mt], pbh);
                    mma_bf16(acc[mt][nt], ah[mt], pbl);
                    mma_bf16(acc[mt][nt], al[mt], pbh);
                }
        }

        const int row0 = t * 128;
        float pa[4] = {0.f, 0.f, 0.f, 0.f}, pd[4] = {0.f, 0.f, 0.f, 0.f};
#pragma unroll
        for (int mt = 0; mt < 2; mt++) {
#pragma unroll
            for (int half = 0; half < 2; half++) {
                int rl = wrow + mt * 16 + half * 8 + (lane >> 2);
                int gr = row0 + rl;
                bool ok = gr < Nn;
#pragma unroll
                for (int nt = 0; nt < 4; nt++) {
                    int cl = wcol + nt * 8 + (lane & 3) * 2;
                    float v0 = acc[mt][nt][half * 2 + 0];
                    float v1 = acc[mt][nt][half * 2 + 1];
                    if (ok) *(__half2*)&g_h[(size_t)gr * 128 + cl] = __floats2half2_rn(v0, v1);
                    pa[mt * 2 + half] += v0 * s_as[cl] + v1 * s_as[cl + 1];
                    pd[mt * 2 + half] += v0 * s_ad[cl] + v1 * s_ad[cl + 1];
                }
            }
        }
        __syncthreads();   // all compute reads of A buffer done; s_ua/s_ud zero visible
#pragma unroll
        for (int i = 0; i < 4; i++) {
            int rl = wrow + (i >> 1) * 16 + (i & 1) * 8 + (lane >> 2);
            atomicAdd(&s_ua[rl], pa[i]);
            atomicAdd(&s_ud[rl], pd[i]);
        }
        __syncthreads();
        if (tid < 128 && row0 + tid < Nn) {
            g_asrc[row0 + tid] = s_ua[tid];
            g_adst[row0 + tid] = s_ud[tid];
        }
        buf ^= 1;
    }
}

// ---------------- softmax aggregation: one warp per dst; deg<=32 fast path ----------
__global__ void k_aggregate(const float* __restrict__ bias, float* __restrict__ outp,
                            int N, int write_final) {
    int warp = (blockIdx.x * blockDim.x + threadIdx.x) >> 5;
    int lane = threadIdx.x & 31;
    if (warp >= N) return;

    int beg = g_rowptr[warp];
    int end = g_rowptr[warp + 1];
    float ad = g_adst[warp];

    float4 acc = make_float4(0.f, 0.f, 0.f, 0.f);
    float denom = 0.f;

    if (end - beg <= 32) {
        int e = beg + lane;
        int s = 0;
        float v = -1e30f;
        if (e < end) {
            s = __ldg(&g_srcs[e]);
            float t = __ldg(&g_asrc[s]) + ad;
            v = t > 0.f ? t : 0.2f * t;
        }
        float m = v;
#pragma unroll
        for (int off = 16; off; off >>= 1)
            m = fmaxf(m, __shfl_xor_sync(0xffffffffu, m, off));
        float w = __expf(v - m);
        denom = w;
        int cnt = end - beg;
        for (int i = 0; i < cnt; i++) {
            float wi = __shfl_sync(0xffffffffu, w, i);
            int   si = __shfl_sync(0xffffffffu, s, i);
            uint2 raw = __ldg((const uint2*)&g_h[(size_t)si * 128 + lane * 4]);
            __half2 h01 = *reinterpret_cast<__half2*>(&raw.x);
            __half2 h23 = *reinterpret_cast<__half2*>(&raw.y);
            float2 f01 = __half22float2(h01);
            float2 f23 = __half22float2(h23);
            acc.x += wi * f01.x; acc.y += wi * f01.y;
            acc.z += wi * f23.x; acc.w += wi * f23.y;
        }
    } else {
        float m = -1e30f;
        for (int e = beg + lane; e < end; e += 32) {
            int s = __ldg(&g_srcs[e]);
            float v = __ldg(&g_asrc[s]) + ad;
            v = v > 0.f ? v : 0.2f * v;
            m = fmaxf(m, v);
        }
#pragma unroll
        for (int off = 16; off; off >>= 1)
            m = fmaxf(m, __shfl_xor_sync(0xffffffffu, m, off));
        for (int base = beg; base < end; base += 32) {
            int e = base + lane;
            float w = 0.f;
            int s = 0;
            if (e < end) {
                s = __ldg(&g_srcs[e]);
                float v = __ldg(&g_asrc[s]) + ad;
                v = v > 0.f ? v : 0.2f * v;
                w = __expf(v - m);
            }
            denom += w;
            int cnt = min(32, end - base);
            for (int i = 0; i < cnt; i++) {
                float wi = __shfl_sync(0xffffffffu, w, i);
                int   si = __shfl_sync(0xffffffffu, s, i);
                uint2 raw = __ldg((const uint2*)&g_h[(size_t)si * 128 + lane * 4]);
                __half2 h01 = *reinterpret_cast<__half2*>(&raw.x);
                __half2 h23 = *reinterpret_cast<__half2*>(&raw.y);
                float2 f01 = __half22float2(h01);
                float2 f23 = __half22float2(h23);
                acc.x += wi * f01.x; acc.y += wi * f01.y;
                acc.z += wi * f23.x; acc.w += wi * f23.y;
            }
        }
    }
#pragma unroll
    for (int off = 16; off; off >>= 1)
        denom += __shfl_xor_sync(0xffffffffu, denom, off);

    float inv = 1.f / denom;
    float4 bv = *(const float4*)&bias[lane * 4];
    float4 r;
    r.x = acc.x * inv + bv.x;
    r.y = acc.y * inv + bv.y;
    r.z = acc.z * inv + bv.z;
    r.w = acc.w * inv + bv.w;
    if (write_final) {
        *(float4*)&outp[(size_t)warp * 128 + lane * 4] = r;
    } else {
        r.x = r.x > 0.f ? r.x : expm1f(r.x);
        r.y = r.y > 0.f ? r.y : expm1f(r.y);
        r.z = r.z > 0.f ? r.z : expm1f(r.z);
        r.w = r.w > 0.f ? r.w : expm1f(r.w);
        size_t idx = (size_t)warp * 128 + lane * 4;
        split4_store(r, &g_xh[idx], &g_xl[idx]);
    }
}

// ---------------- launch: CSR + prepW overlapped on a side stream ----------------
extern "C" void kernel_launch(void* const* d_in, const int* in_sizes, int n_in,
                              void* d_out, int out_size) {
    const float* x  = (const float*)d_in[0];
    const int*   ei = (const int*)d_in[1];
    int N  = in_sizes[0] / F;
    int E  = in_sizes[1] / 2;
    int ET = E + N;
    int nb = (N + 1023) / 1024;
    int ntiles = (N + 127) / 128;

    static cudaStream_t s1;
    static cudaEvent_t e0, e1;
    static int inited = 0;
    if (!inited) {
        cudaFuncSetAttribute(k_gemm_mma, cudaFuncAttributeMaxDynamicSharedMemorySize, GEMM_SMEM);
        cudaStreamCreateWithFlags(&s1, cudaStreamNonBlocking);
        cudaEventCreateWithFlags(&e0, cudaEventDisableTiming);
        cudaEventCreateWithFlags(&e1, cudaEventDisableTiming);
        inited = 1;
    }

    int warp_blocks = (N * 32 + 255) / 256;

    // fork: prepW (layers 1-2) + CSR chain on side stream
    cudaEventRecord(e0, 0);
    cudaStreamWaitEvent(s1, e0, 0);
    k_prepW_all<<<48, 256, 0, s1>>>((const float*)d_in[2], (const float*)d_in[6], (const float*)d_in[10]);
    k_zero_deg<<<(N + 255) / 256, 256, 0, s1>>>(N);
    k_count<<<(ET + 255) / 256, 256, 0, s1>>>(ei, E, N);
    k_scan1<<<nb, 256, 0, s1>>>(N);
    k_scan3<<<nb, 256, 0, s1>>>(N, nb);
    k_scatter<<<(ET + 255) / 256, 256, 0, s1>>>(ei, E, N);
    cudaEventRecord(e1, s1);

    // main stream: GEMM0 starts immediately (stages A and B from fp32 inline)
    k_gemm_mma<<<148, 512, GEMM_SMEM>>>(0, x, (const float*)d_in[2],
                                        (const float*)d_in[3], (const float*)d_in[4], N, ntiles);

    // join: aggregate needs CSR; gemm1/2 need prepW
    cudaStreamWaitEvent(0, e1, 0);

    for (int l = 0; l < 3; l++) {
        const float* as = (const float*)d_in[3 + 4 * l];
        const float* ad = (const float*)d_in[4 + 4 * l];
        const float* b  = (const float*)d_in[5 + 4 * l];
        if (l > 0)
            k_gemm_mma<<<148, 512, GEMM_SMEM>>>(l, nullptr, nullptr, as, ad, N, ntiles);
        k_aggregate<<<warp_blocks, 256>>>(b, l == 2 ? (float*)d_out : nullptr, N, l == 2 ? 1 : 0);
    }
}